// round 1
// baseline (speedup 1.0000x reference)
#include <cuda_runtime.h>
#include <cuda_bf16.h>

// ReBasedLinearAttention: B=2, L=2048, D=1024, H=16, FD=16, HD=64
//   q = h@Wq [BL,256], k = h@Wk [BL,256], v = h@Wv [BL,1024]
//   s = ((q.k) * FD^-0.5)^2, causal; z = rowsum(s); o = (s@v)/(z+eps)
//   out = o @ Wo
// All fp32. Packed f32x2 FMA (FFMA2) in all inner loops for full-rate FP32 on sm_103a.

#define Bb 2
#define Ll 2048
#define Dd 1024
#define Hh 16
#define FDIM 16
#define HDIM 64
#define BL (Bb * Ll)

typedef unsigned long long ull;

__device__ __forceinline__ ull pack2(float lo, float hi) {
    ull r;
    asm("mov.b64 %0, {%1,%2};" : "=l"(r) : "f"(lo), "f"(hi));
    return r;
}
__device__ __forceinline__ void unpack2(ull v, float& lo, float& hi) {
    asm("mov.b64 {%0,%1}, %2;" : "=f"(lo), "=f"(hi) : "l"(v));
}
__device__ __forceinline__ ull fma2(ull a, ull b, ull c) {
    ull d;
    asm("fma.rn.f32x2 %0, %1, %2, %3;" : "=l"(d) : "l"(a), "l"(b), "l"(c));
    return d;
}

// Scratch (device globals: no allocation allowed in kernel_launch)
__device__ float g_q[BL * 256];   //  4 MB  [b*L+l][h*16+f]
__device__ float g_k[BL * 256];   //  4 MB
__device__ float g_v[BL * 1024];  // 16 MB  [b*L+l][h*64+d]
__device__ float g_o[BL * 1024];  // 16 MB  [b*L+l][h*64+d]

// ---------------------------------------------------------------------------
// SGEMM: C = A @ B, row-major, M%128==0, N%128==0, K%16==0.
// 128x128 block tile, BK=16, 256 threads, 8x8 microtile (cols split tx*4 / tx*4+64).
// blockIdx.z selects (B0,C0) vs (B1,C1) so Wq/Wk run as one launch.
// ---------------------------------------------------------------------------
__global__ __launch_bounds__(256, 2)
void sgemm128(const float* __restrict__ A,
              const float* __restrict__ B0, const float* __restrict__ B1,
              float* __restrict__ C0, float* __restrict__ C1,
              int M, int N, int K)
{
    const float* __restrict__ Bm = (blockIdx.z == 0) ? B0 : B1;
    float* __restrict__ Cm = (blockIdx.z == 0) ? C0 : C1;

    __shared__ float As[16][128];
    __shared__ float Bs[16][128];

    const int tid = threadIdx.x;
    const int tx = tid & 15;
    const int ty = tid >> 4;
    const int rowBase = blockIdx.y * 128;
    const int colBase = blockIdx.x * 128;

    ull acc[8][4];
#pragma unroll
    for (int i = 0; i < 8; i++)
#pragma unroll
        for (int j = 0; j < 4; j++) acc[i][j] = 0ULL;

    const int ar = tid >> 2;           // 0..63 (and +64)
    const int ac = (tid & 3) * 4;      // 0,4,8,12
    const int br = tid >> 5;           // 0..7 (and +8)
    const int bc = (tid & 31) * 4;     // 0..124

    for (int k0 = 0; k0 < K; k0 += 16) {
        // gmem prefetch into regs (overlaps with previous compute)
        float4 av0 = *(const float4*)&A[(size_t)(rowBase + ar) * K + k0 + ac];
        float4 av1 = *(const float4*)&A[(size_t)(rowBase + ar + 64) * K + k0 + ac];
        float4 bv0 = *(const float4*)&Bm[(size_t)(k0 + br) * N + colBase + bc];
        float4 bv1 = *(const float4*)&Bm[(size_t)(k0 + br + 8) * N + colBase + bc];

        __syncthreads();  // previous compute done reading smem

        As[ac + 0][ar] = av0.x; As[ac + 1][ar] = av0.y;
        As[ac + 2][ar] = av0.z; As[ac + 3][ar] = av0.w;
        As[ac + 0][ar + 64] = av1.x; As[ac + 1][ar + 64] = av1.y;
        As[ac + 2][ar + 64] = av1.z; As[ac + 3][ar + 64] = av1.w;
        *(float4*)&Bs[br][bc] = bv0;
        *(float4*)&Bs[br + 8][bc] = bv1;

        __syncthreads();

#pragma unroll
        for (int kk = 0; kk < 16; kk++) {
            float4 a0 = *(const float4*)&As[kk][ty * 8];
            float4 a1 = *(const float4*)&As[kk][ty * 8 + 4];
            float4 b0 = *(const float4*)&Bs[kk][tx * 4];
            float4 b1 = *(const float4*)&Bs[kk][tx * 4 + 64];
            ull b2[4];
            b2[0] = pack2(b0.x, b0.y);
            b2[1] = pack2(b0.z, b0.w);
            b2[2] = pack2(b1.x, b1.y);
            b2[3] = pack2(b1.z, b1.w);
            float a[8] = {a0.x, a0.y, a0.z, a0.w, a1.x, a1.y, a1.z, a1.w};
#pragma unroll
            for (int i = 0; i < 8; i++) {
                ull a2 = pack2(a[i], a[i]);
#pragma unroll
                for (int j = 0; j < 4; j++)
                    acc[i][j] = fma2(a2, b2[j], acc[i][j]);
            }
        }
    }

#pragma unroll
    for (int i = 0; i < 8; i++) {
        size_t rofs = (size_t)(rowBase + ty * 8 + i) * N + colBase;
        float f0, f1, f2, f3, f4, f5, f6, f7;
        unpack2(acc[i][0], f0, f1);
        unpack2(acc[i][1], f2, f3);
        unpack2(acc[i][2], f4, f5);
        unpack2(acc[i][3], f6, f7);
        *(float4*)&Cm[rofs + tx * 4]      = make_float4(f0, f1, f2, f3);
        *(float4*)&Cm[rofs + tx * 4 + 64] = make_float4(f4, f5, f6, f7);
    }
}

// ---------------------------------------------------------------------------
// Attention: one CTA = one (b, h, 64-query tile). 256 threads.
// Per key tile of 64: stage k[64x16], v[64x64]; compute s[j][q]=(q.k)^2/16
// (causal) into smem; then sv-phase with 4q x 4d register tile per thread.
// Padded smem strides (20 / 68 floats) keep LDS/STS conflict-free.
// ---------------------------------------------------------------------------
__global__ __launch_bounds__(256, 2)
void attn64(const float* __restrict__ gq, const float* __restrict__ gk,
            const float* __restrict__ gv, float* __restrict__ go)
{
    const int qt = 31 - (int)blockIdx.x;  // heaviest blocks first
    const int h = blockIdx.y;
    const int b = blockIdx.z;
    const int qi0 = qt * 64;

    __shared__ float qs[64][20];
    __shared__ float ks[64][20];
    __shared__ float vs[64][64];
    __shared__ float ss[64][68];   // [j][q]

    const int tid = threadIdx.x;

    // load q tile (64 x 16)
    {
        int r = tid >> 2;
        int c = (tid & 3) * 4;
        float4 qv = *(const float4*)&gq[(size_t)(b * Ll + qi0 + r) * 256 + h * 16 + c];
        *(float4*)&qs[r][c] = qv;
    }

    const int qg  = tid >> 4;       // 0..15 -> queries qg*4..+3
    const int dgr = tid & 15;       // 0..15 -> dims dgr*4..+3
    const int jS  = tid & 63;       // s-phase key row
    const int qh  = (tid >> 6) * 16;// s-phase query offset

    ull o2[4][2];
#pragma unroll
    for (int i = 0; i < 4; i++) { o2[i][0] = 0ULL; o2[i][1] = 0ULL; }
    float z0 = 0.f, z1 = 0.f, z2 = 0.f, z3 = 0.f;

    for (int j0 = 0; j0 <= qi0; j0 += 64) {
        // prefetch k/v tile into regs
        int r = tid >> 2;
        int c = (tid & 3) * 4;
        float4 kv = *(const float4*)&gk[(size_t)(b * Ll + j0 + r) * 256 + h * 16 + c];
        float4 vvld[4];
#pragma unroll
        for (int t = 0; t < 4; t++) {
            int idx = tid + t * 256;
            int vr = idx >> 4;
            int vc = (idx & 15) * 4;
            vvld[t] = *(const float4*)&gv[(size_t)(b * Ll + j0 + vr) * 1024 + h * 64 + vc];
        }

        __syncthreads();  // prev sv-phase done with ss/vs (also covers q store, iter 0)

        *(float4*)&ks[r][c] = kv;
#pragma unroll
        for (int t = 0; t < 4; t++) {
            int idx = tid + t * 256;
            int vr = idx >> 4;
            int vc = (idx & 15) * 4;
            *(float4*)&vs[vr][vc] = vvld[t];
        }
        __syncthreads();

        // ---- s-phase: s[jS][q] for q in [qh, qh+16) ----
        {
            float4 k0v = *(const float4*)&ks[jS][0];
            float4 k1v = *(const float4*)&ks[jS][4];
            float4 k2v = *(const float4*)&ks[jS][8];
            float4 k3v = *(const float4*)&ks[jS][12];
            const int jg = j0 + jS;
#pragma unroll
            for (int qb = 0; qb < 4; qb++) {
                float sv[4];
#pragma unroll
                for (int u = 0; u < 4; u++) {
                    int q = qh + qb * 4 + u;
                    float4 p0 = *(const float4*)&qs[q][0];
                    float4 p1 = *(const float4*)&qs[q][4];
                    float4 p2 = *(const float4*)&qs[q][8];
                    float4 p3 = *(const float4*)&qs[q][12];
                    float d = p0.x * k0v.x;
                    d = fmaf(p0.y, k0v.y, d);
                    d = fmaf(p0.z, k0v.z, d);
                    d = fmaf(p0.w, k0v.w, d);
                    d = fmaf(p1.x, k1v.x, d);
                    d = fmaf(p1.y, k1v.y, d);
                    d = fmaf(p1.z, k1v.z, d);
                    d = fmaf(p1.w, k1v.w, d);
                    d = fmaf(p2.x, k2v.x, d);
                    d = fmaf(p2.y, k2v.y, d);
                    d = fmaf(p2.z, k2v.z, d);
                    d = fmaf(p2.w, k2v.w, d);
                    d = fmaf(p3.x, k3v.x, d);
                    d = fmaf(p3.y, k3v.y, d);
                    d = fmaf(p3.z, k3v.z, d);
                    d = fmaf(p3.w, k3v.w, d);
                    d = d * d * 0.0625f;              // (qk_scale^2 = 1/16)
                    sv[u] = (jg <= qi0 + q) ? d : 0.f; // causal
                }
                *(float4*)&ss[jS][qh + qb * 4] = make_float4(sv[0], sv[1], sv[2], sv[3]);
            }
        }
        __syncthreads();

        // ---- sv-phase: o[4q][4d] += s * v ; z += s ----
#pragma unroll 8
        for (int j = 0; j < 64; j++) {
            float4 s4 = *(const float4*)&ss[j][qg * 4];
            float4 v4 = *(const float4*)&vs[j][dgr * 4];
            ull vlo = pack2(v4.x, v4.y);
            ull vhi = pack2(v4.z, v4.w);
            z0 += s4.x; z1 += s4.y; z2 += s4.z; z3 += s4.w;
            ull sx = pack2(s4.x, s4.x);
            o2[0][0] = fma2(sx, vlo, o2[0][0]);
            o2[0][1] = fma2(sx, vhi, o2[0][1]);
            ull sy = pack2(s4.y, s4.y);
            o2[1][0] = fma2(sy, vlo, o2[1][0]);
            o2[1][1] = fma2(sy, vhi, o2[1][1]);
            ull sz = pack2(s4.z, s4.z);
            o2[2][0] = fma2(sz, vlo, o2[2][0]);
            o2[2][1] = fma2(sz, vhi, o2[2][1]);
            ull sw = pack2(s4.w, s4.w);
            o2[3][0] = fma2(sw, vlo, o2[3][0]);
            o2[3][1] = fma2(sw, vhi, o2[3][1]);
        }
    }

    // epilogue: normalize and write o
    float zz[4] = {z0, z1, z2, z3};
#pragma unroll
    for (int i = 0; i < 4; i++) {
        float inv = 1.f / (zz[i] + 1e-5f);
        float f0, f1, f2, f3;
        unpack2(o2[i][0], f0, f1);
        unpack2(o2[i][1], f2, f3);
        int l = qi0 + qg * 4 + i;
        *(float4*)&go[(size_t)(b * Ll + l) * 1024 + h * 64 + dgr * 4] =
            make_float4(f0 * inv, f1 * inv, f2 * inv, f3 * inv);
    }
}

// ---------------------------------------------------------------------------
extern "C" void kernel_launch(void* const* d_in, const int* in_sizes, int n_in,
                              void* d_out, int out_size)
{
    const float* hidden = (const float*)d_in[0];
    const float* Wq = (const float*)d_in[1];
    const float* Wk = (const float*)d_in[2];
    const float* Wv = (const float*)d_in[3];
    const float* Wo = (const float*)d_in[4];
    float* out = (float*)d_out;

    float *pq, *pk, *pv, *po;
    cudaGetSymbolAddress((void**)&pq, g_q);
    cudaGetSymbolAddress((void**)&pk, g_k);
    cudaGetSymbolAddress((void**)&pv, g_v);
    cudaGetSymbolAddress((void**)&po, g_o);

    // Q and K projections (one launch, z picks weights/output): [4096x1024]x[1024x256]
    sgemm128<<<dim3(2, 32, 2), 256>>>(hidden, Wq, Wk, pq, pk, BL, 256, Dd);
    // V projection: [4096x1024]x[1024x1024]
    sgemm128<<<dim3(8, 32, 1), 256>>>(hidden, Wv, Wv, pv, pv, BL, 1024, Dd);
    // Attention
    attn64<<<dim3(32, Hh, Bb), 256>>>(pq, pk, pv, po);
    // Output projection: [4096x1024]x[1024x1024]
    sgemm128<<<dim3(8, 32, 1), 256>>>(po, Wo, Wo, out, out, BL, Dd, Dd);
}

// round 3
// speedup vs baseline: 1.3589x; 1.3589x over previous
#include <cuda_runtime.h>
#include <cuda_bf16.h>
#include <stdint.h>

// ReBasedLinearAttention: B=2, L=2048, D=1024, H=16, FD=16, HD=64
// GEMMs via mma.sync bf16 hi/lo split (3-MMA fp32 emulation, sm_80+ PTX).
// Attention in fp32 with packed FFMA2.

#define Bb 2
#define Ll 2048
#define Dd 1024
#define Hh 16
#define BL (Bb * Ll)

typedef unsigned long long ull;

// ---------------- packed fp32 helpers ----------------
__device__ __forceinline__ ull pack2(float lo, float hi) {
    ull r; asm("mov.b64 %0, {%1,%2};" : "=l"(r) : "f"(lo), "f"(hi)); return r;
}
__device__ __forceinline__ void unpack2(ull v, float& lo, float& hi) {
    asm("mov.b64 {%0,%1}, %2;" : "=f"(lo), "=f"(hi) : "l"(v));
}
__device__ __forceinline__ ull fma2(ull a, ull b, ull c) {
    ull d; asm("fma.rn.f32x2 %0, %1, %2, %3;" : "=l"(d) : "l"(a), "l"(b), "l"(c)); return d;
}

// ---------------- scratch ----------------
__device__ float g_q[BL * 256];
__device__ float g_k[BL * 256];
__device__ float g_v[BL * 1024];
__device__ float g_o[BL * 1024];

__device__ __nv_bfloat16 g_hhi[BL * 1024];
__device__ __nv_bfloat16 g_hlo[BL * 1024];
__device__ __nv_bfloat16 g_ohi[BL * 1024];
__device__ __nv_bfloat16 g_olo[BL * 1024];

__device__ __nv_bfloat16 g_wqt_hi[256 * 1024];
__device__ __nv_bfloat16 g_wqt_lo[256 * 1024];
__device__ __nv_bfloat16 g_wkt_hi[256 * 1024];
__device__ __nv_bfloat16 g_wkt_lo[256 * 1024];
__device__ __nv_bfloat16 g_wvt_hi[1024 * 1024];
__device__ __nv_bfloat16 g_wvt_lo[1024 * 1024];
__device__ __nv_bfloat16 g_wot_hi[1024 * 1024];
__device__ __nv_bfloat16 g_wot_lo[1024 * 1024];

// ---------------- PTX helpers ----------------
__device__ __forceinline__ uint32_t smem_u32(const void* p) {
    uint32_t a;
    asm("{ .reg .u64 t; cvta.to.shared.u64 t, %1; cvt.u32.u64 %0, t; }" : "=r"(a) : "l"(p));
    return a;
}
__device__ __forceinline__ void cp_async16(uint32_t saddr, const void* gaddr) {
    asm volatile("cp.async.cg.shared.global [%0], [%1], 16;" :: "r"(saddr), "l"(gaddr) : "memory");
}
__device__ __forceinline__ void cp_commit() {
    asm volatile("cp.async.commit_group;" ::: "memory");
}
__device__ __forceinline__ void ldsm_x4(uint32_t& r0, uint32_t& r1, uint32_t& r2, uint32_t& r3,
                                        uint32_t addr) {
    asm volatile("ldmatrix.sync.aligned.m8n8.x4.shared.b16 {%0,%1,%2,%3}, [%4];"
                 : "=r"(r0), "=r"(r1), "=r"(r2), "=r"(r3) : "r"(addr));
}
__device__ __forceinline__ void mma16816(float c[4], uint32_t a0, uint32_t a1, uint32_t a2,
                                         uint32_t a3, uint32_t b0, uint32_t b1) {
    asm volatile(
        "mma.sync.aligned.m16n8k16.row.col.f32.bf16.bf16.f32 "
        "{%0,%1,%2,%3}, {%4,%5,%6,%7}, {%8,%9}, {%0,%1,%2,%3};"
        : "+f"(c[0]), "+f"(c[1]), "+f"(c[2]), "+f"(c[3])
        : "r"(a0), "r"(a1), "r"(a2), "r"(a3), "r"(b0), "r"(b1));
}

// ---------------------------------------------------------------------------
// fp32 -> bf16 hi/lo split (layout preserved)
// ---------------------------------------------------------------------------
__global__ void split_rows(const float* __restrict__ X,
                           __nv_bfloat16* __restrict__ hi,
                           __nv_bfloat16* __restrict__ lo, int n4)
{
    int i = blockIdx.x * blockDim.x + threadIdx.x;
    if (i >= n4) return;
    float4 v = ((const float4*)X)[i];
    float vv[4] = {v.x, v.y, v.z, v.w};
    __nv_bfloat16 hh[4], llv[4];
#pragma unroll
    for (int j = 0; j < 4; j++) {
        __nv_bfloat16 h = __float2bfloat16(vv[j]);
        hh[j] = h;
        llv[j] = __float2bfloat16(vv[j] - __bfloat162float(h));
    }
    *(ull*)&hi[i * 4] = *(ull*)hh;
    *(ull*)&lo[i * 4] = *(ull*)llv;
}

// ---------------------------------------------------------------------------
// W [K,N] fp32 -> Wt hi/lo [N,K] bf16 (transpose + split)
// ---------------------------------------------------------------------------
__global__ void transpose_split(const float* __restrict__ W,
                                __nv_bfloat16* __restrict__ thi,
                                __nv_bfloat16* __restrict__ tlo, int K, int N)
{
    __shared__ float t[32][33];
    int n0 = blockIdx.x * 32, k0 = blockIdx.y * 32;
    int tx = threadIdx.x, ty = threadIdx.y;  // 32 x 8
#pragma unroll
    for (int i = 0; i < 4; i++)
        t[ty + i * 8][tx] = W[(size_t)(k0 + ty + i * 8) * N + n0 + tx];
    __syncthreads();
#pragma unroll
    for (int i = 0; i < 4; i++) {
        int r = ty + i * 8;
        float v = t[tx][r];
        __nv_bfloat16 h = __float2bfloat16(v);
        __nv_bfloat16 l = __float2bfloat16(v - __bfloat162float(h));
        thi[(size_t)(n0 + r) * K + k0 + tx] = h;
        tlo[(size_t)(n0 + r) * K + k0 + tx] = l;
    }
}

// ---------------------------------------------------------------------------
// bf16x3 GEMM via mma.sync: C[M,N] = A[M,K] @ Bt[N,K]^T  (fp32 hi/lo split)
// CTA 128x128, 256 threads (warp grid 2m x 4n, warp tile 64x32), BK=32,
// cp.async double buffer. Rows padded to 80B -> conflict-free ldmatrix.
// blockIdx.z selects (Bt0,C0)/(Bt1,C1).
// ---------------------------------------------------------------------------
#define ROWB 80
#define MATB (128 * ROWB)       // 10240 B per matrix per stage
#define STAGEB (4 * MATB)       // Ah, Al, Bh, Bl
#define GEMM_SMEM (2 * STAGEB)  // 81920 B

__global__ __launch_bounds__(256, 1)
void gemm_mma(const __nv_bfloat16* __restrict__ Ahi, const __nv_bfloat16* __restrict__ Alo,
              const __nv_bfloat16* __restrict__ Bhi0, const __nv_bfloat16* __restrict__ Blo0,
              float* __restrict__ C0,
              const __nv_bfloat16* __restrict__ Bhi1, const __nv_bfloat16* __restrict__ Blo1,
              float* __restrict__ C1,
              int Ktot, int N)
{
    const __nv_bfloat16* __restrict__ Bhi = (blockIdx.z == 0) ? Bhi0 : Bhi1;
    const __nv_bfloat16* __restrict__ Blo = (blockIdx.z == 0) ? Blo0 : Blo1;
    float* __restrict__ C = (blockIdx.z == 0) ? C0 : C1;

    extern __shared__ char smem_raw[];
    const uint32_t sbase = smem_u32(smem_raw);

    const int tid = threadIdx.x;
    const int lane = tid & 31;
    const int warp = tid >> 5;
    const int wm = warp >> 2;   // 0..1
    const int wn = warp & 3;    // 0..3
    const int rowBase = blockIdx.y * 128;
    const int colBase = blockIdx.x * 128;
    const int S = Ktot / 32;

    float acc[4][4][4];
#pragma unroll
    for (int i = 0; i < 4; i++)
#pragma unroll
        for (int j = 0; j < 4; j++)
#pragma unroll
            for (int e = 0; e < 4; e++) acc[i][j][e] = 0.f;

    // ldmatrix per-lane addressing
    const int lrow = (lane & 7) + ((lane >> 3) & 1) * 8;  // 0..15
    const int lkb = ((lane >> 4) & 1) * 16;               // 0 or 16 bytes

    // loader mapping: 8 x 16B chunks per thread per stage
    // t: 0,1 -> Ahi ; 2,3 -> Alo ; 4,5 -> Bhi ; 6,7 -> Blo
#define LOAD_STAGE(s, buf)                                                              \
    do {                                                                                \
        const int k0 = (s) * 32;                                                        \
        const uint32_t sb_ = sbase + (buf) * STAGEB;                                    \
        _Pragma("unroll")                                                               \
        for (int t = 0; t < 8; t++) {                                                   \
            int mat = t >> 1;                                                           \
            int sub = (t & 1) * 256 + tid;                                              \
            int row = sub >> 2;                                                         \
            int kc = sub & 3;                                                           \
            const __nv_bfloat16* src = (mat == 0) ? Ahi : (mat == 1) ? Alo              \
                                     : (mat == 2) ? Bhi : Blo;                          \
            int grow = ((mat < 2) ? rowBase : colBase) + row;                           \
            const __nv_bfloat16* g = src + (size_t)grow * Ktot + k0 + kc * 8;           \
            uint32_t sa = sb_ + mat * MATB + row * ROWB + kc * 16;                      \
            cp_async16(sa, g);                                                          \
        }                                                                               \
        cp_commit();                                                                    \
    } while (0)

    LOAD_STAGE(0, 0);

    for (int s = 0; s < S; s++) {
        if (s + 1 < S) {
            LOAD_STAGE(s + 1, (s + 1) & 1);
            asm volatile("cp.async.wait_group 1;" ::: "memory");
        } else {
            asm volatile("cp.async.wait_group 0;" ::: "memory");
        }
        __syncthreads();

        const uint32_t sb = sbase + (s & 1) * STAGEB;
#pragma unroll
        for (int s2 = 0; s2 < 2; s2++) {
            const uint32_t kbyte = s2 * 32 + lkb;

            uint32_t Ah[4][4], Al[4][4];
#pragma unroll
            for (int mf = 0; mf < 4; mf++) {
                uint32_t ra = sb + (uint32_t)((wm * 64 + mf * 16 + lrow) * ROWB) + kbyte;
                ldsm_x4(Ah[mf][0], Ah[mf][1], Ah[mf][2], Ah[mf][3], ra);
                ldsm_x4(Al[mf][0], Al[mf][1], Al[mf][2], Al[mf][3], ra + MATB);
            }
            uint32_t Bh[4][2], Blr[4][2];
#pragma unroll
            for (int nf2 = 0; nf2 < 2; nf2++) {
                uint32_t rb = sb + 2 * MATB +
                              (uint32_t)((wn * 32 + nf2 * 16 + lrow) * ROWB) + kbyte;
                uint32_t q0, q1, q2, q3;
                ldsm_x4(q0, q1, q2, q3, rb);
                Bh[nf2 * 2 + 0][0] = q0; Bh[nf2 * 2 + 0][1] = q2;
                Bh[nf2 * 2 + 1][0] = q1; Bh[nf2 * 2 + 1][1] = q3;
                ldsm_x4(q0, q1, q2, q3, rb + MATB);
                Blr[nf2 * 2 + 0][0] = q0; Blr[nf2 * 2 + 0][1] = q2;
                Blr[nf2 * 2 + 1][0] = q1; Blr[nf2 * 2 + 1][1] = q3;
            }

#pragma unroll
            for (int mf = 0; mf < 4; mf++)
#pragma unroll
                for (int nf = 0; nf < 4; nf++) {
                    mma16816(acc[mf][nf], Ah[mf][0], Ah[mf][1], Ah[mf][2], Ah[mf][3],
                             Bh[nf][0], Bh[nf][1]);
                    mma16816(acc[mf][nf], Ah[mf][0], Ah[mf][1], Ah[mf][2], Ah[mf][3],
                             Blr[nf][0], Blr[nf][1]);
                    mma16816(acc[mf][nf], Al[mf][0], Al[mf][1], Al[mf][2], Al[mf][3],
                             Bh[nf][0], Bh[nf][1]);
                }
        }
        __syncthreads();
    }

    // epilogue
    const int r0b = rowBase + wm * 64 + (lane >> 2);
    const int c0b = colBase + wn * 32 + (lane & 3) * 2;
#pragma unroll
    for (int mf = 0; mf < 4; mf++) {
#pragma unroll
        for (int nf = 0; nf < 4; nf++) {
            int r = r0b + mf * 16;
            int c = c0b + nf * 8;
            *(float2*)&C[(size_t)r * N + c] = make_float2(acc[mf][nf][0], acc[mf][nf][1]);
            *(float2*)&C[(size_t)(r + 8) * N + c] = make_float2(acc[mf][nf][2], acc[mf][nf][3]);
        }
    }
}

// ---------------------------------------------------------------------------
// Attention (fp32, packed FFMA2) — unchanged.
// ---------------------------------------------------------------------------
__global__ __launch_bounds__(256, 2)
void attn64(const float* __restrict__ gq, const float* __restrict__ gk,
            const float* __restrict__ gv, float* __restrict__ go)
{
    const int qt = 31 - (int)blockIdx.x;
    const int h = blockIdx.y;
    const int b = blockIdx.z;
    const int qi0 = qt * 64;

    __shared__ float qs[64][20];
    __shared__ float ks[64][20];
    __shared__ float vs[64][64];
    __shared__ float ss[64][68];

    const int tid = threadIdx.x;

    {
        int r = tid >> 2;
        int c = (tid & 3) * 4;
        float4 qv = *(const float4*)&gq[(size_t)(b * Ll + qi0 + r) * 256 + h * 16 + c];
        *(float4*)&qs[r][c] = qv;
    }

    const int qg  = tid >> 4;
    const int dgr = tid & 15;
    const int jS  = tid & 63;
    const int qh  = (tid >> 6) * 16;

    ull o2[4][2];
#pragma unroll
    for (int i = 0; i < 4; i++) { o2[i][0] = 0ULL; o2[i][1] = 0ULL; }
    float z0 = 0.f, z1 = 0.f, z2 = 0.f, z3 = 0.f;

    for (int j0 = 0; j0 <= qi0; j0 += 64) {
        int r = tid >> 2;
        int c = (tid & 3) * 4;
        float4 kv = *(const float4*)&gk[(size_t)(b * Ll + j0 + r) * 256 + h * 16 + c];
        float4 vvld[4];
#pragma unroll
        for (int t = 0; t < 4; t++) {
            int idx = tid + t * 256;
            int vr = idx >> 4;
            int vc = (idx & 15) * 4;
            vvld[t] = *(const float4*)&gv[(size_t)(b * Ll + j0 + vr) * 1024 + h * 64 + vc];
        }

        __syncthreads();

        *(float4*)&ks[r][c] = kv;
#pragma unroll
        for (int t = 0; t < 4; t++) {
            int idx = tid + t * 256;
            int vr = idx >> 4;
            int vc = (idx & 15) * 4;
            *(float4*)&vs[vr][vc] = vvld[t];
        }
        __syncthreads();

        {
            float4 k0v = *(const float4*)&ks[jS][0];
            float4 k1v = *(const float4*)&ks[jS][4];
            float4 k2v = *(const float4*)&ks[jS][8];
            float4 k3v = *(const float4*)&ks[jS][12];
            const int jg = j0 + jS;
#pragma unroll
            for (int qb = 0; qb < 4; qb++) {
                float sv[4];
#pragma unroll
                for (int u = 0; u < 4; u++) {
                    int q = qh + qb * 4 + u;
                    float4 p0 = *(const float4*)&qs[q][0];
                    float4 p1 = *(const float4*)&qs[q][4];
                    float4 p2 = *(const float4*)&qs[q][8];
                    float4 p3 = *(const float4*)&qs[q][12];
                    float d = p0.x * k0v.x;
                    d = fmaf(p0.y, k0v.y, d);
                    d = fmaf(p0.z, k0v.z, d);
                    d = fmaf(p0.w, k0v.w, d);
                    d = fmaf(p1.x, k1v.x, d);
                    d = fmaf(p1.y, k1v.y, d);
                    d = fmaf(p1.z, k1v.z, d);
                    d = fmaf(p1.w, k1v.w, d);
                    d = fmaf(p2.x, k2v.x, d);
                    d = fmaf(p2.y, k2v.y, d);
                    d = fmaf(p2.z, k2v.z, d);
                    d = fmaf(p2.w, k2v.w, d);
                    d = fmaf(p3.x, k3v.x, d);
                    d = fmaf(p3.y, k3v.y, d);
                    d = fmaf(p3.z, k3v.z, d);
                    d = fmaf(p3.w, k3v.w, d);
                    d = d * d * 0.0625f;
                    sv[u] = (jg <= qi0 + q) ? d : 0.f;
                }
                *(float4*)&ss[jS][qh + qb * 4] = make_float4(sv[0], sv[1], sv[2], sv[3]);
            }
        }
        __syncthreads();

#pragma unroll 8
        for (int j = 0; j < 64; j++) {
            float4 s4 = *(const float4*)&ss[j][qg * 4];
            float4 v4 = *(const float4*)&vs[j][dgr * 4];
            ull vlo = pack2(v4.x, v4.y);
            ull vhi = pack2(v4.z, v4.w);
            z0 += s4.x; z1 += s4.y; z2 += s4.z; z3 += s4.w;
            ull sx = pack2(s4.x, s4.x);
            o2[0][0] = fma2(sx, vlo, o2[0][0]);
            o2[0][1] = fma2(sx, vhi, o2[0][1]);
            ull sy = pack2(s4.y, s4.y);
            o2[1][0] = fma2(sy, vlo, o2[1][0]);
            o2[1][1] = fma2(sy, vhi, o2[1][1]);
            ull sz = pack2(s4.z, s4.z);
            o2[2][0] = fma2(sz, vlo, o2[2][0]);
            o2[2][1] = fma2(sz, vhi, o2[2][1]);
            ull sw = pack2(s4.w, s4.w);
            o2[3][0] = fma2(sw, vlo, o2[3][0]);
            o2[3][1] = fma2(sw, vhi, o2[3][1]);
        }
    }

    float zz[4] = {z0, z1, z2, z3};
#pragma unroll
    for (int i = 0; i < 4; i++) {
        float inv = 1.f / (zz[i] + 1e-5f);
        float f0, f1, f2, f3;
        unpack2(o2[i][0], f0, f1);
        unpack2(o2[i][1], f2, f3);
        int l = qi0 + qg * 4 + i;
        *(float4*)&go[(size_t)(b * Ll + l) * 1024 + h * 64 + dgr * 4] =
            make_float4(f0 * inv, f1 * inv, f2 * inv, f3 * inv);
    }
}

// ---------------------------------------------------------------------------
extern "C" void kernel_launch(void* const* d_in, const int* in_sizes, int n_in,
                              void* d_out, int out_size)
{
    const float* hidden = (const float*)d_in[0];
    const float* Wq = (const float*)d_in[1];
    const float* Wk = (const float*)d_in[2];
    const float* Wv = (const float*)d_in[3];
    const float* Wo = (const float*)d_in[4];
    float* out = (float*)d_out;

    float *pq, *pk, *pv, *po;
    cudaGetSymbolAddress((void**)&pq, g_q);
    cudaGetSymbolAddress((void**)&pk, g_k);
    cudaGetSymbolAddress((void**)&pv, g_v);
    cudaGetSymbolAddress((void**)&po, g_o);
    __nv_bfloat16 *hhi, *hlo, *ohi, *olo;
    cudaGetSymbolAddress((void**)&hhi, g_hhi);
    cudaGetSymbolAddress((void**)&hlo, g_hlo);
    cudaGetSymbolAddress((void**)&ohi, g_ohi);
    cudaGetSymbolAddress((void**)&olo, g_olo);
    __nv_bfloat16 *wqh, *wql, *wkh, *wkl, *wvh, *wvl, *woh, *wol;
    cudaGetSymbolAddress((void**)&wqh, g_wqt_hi);
    cudaGetSymbolAddress((void**)&wql, g_wqt_lo);
    cudaGetSymbolAddress((void**)&wkh, g_wkt_hi);
    cudaGetSymbolAddress((void**)&wkl, g_wkt_lo);
    cudaGetSymbolAddress((void**)&wvh, g_wvt_hi);
    cudaGetSymbolAddress((void**)&wvl, g_wvt_lo);
    cudaGetSymbolAddress((void**)&woh, g_wot_hi);
    cudaGetSymbolAddress((void**)&wol, g_wot_lo);

    cudaFuncSetAttribute(gemm_mma, cudaFuncAttributeMaxDynamicSharedMemorySize, GEMM_SMEM);

    // conversions
    split_rows<<<(BL * 1024 / 4 + 255) / 256, 256>>>(hidden, hhi, hlo, BL * 1024 / 4);
    transpose_split<<<dim3(256 / 32, 1024 / 32), dim3(32, 8)>>>(Wq, wqh, wql, 1024, 256);
    transpose_split<<<dim3(256 / 32, 1024 / 32), dim3(32, 8)>>>(Wk, wkh, wkl, 1024, 256);
    transpose_split<<<dim3(1024 / 32, 1024 / 32), dim3(32, 8)>>>(Wv, wvh, wvl, 1024, 1024);
    transpose_split<<<dim3(1024 / 32, 1024 / 32), dim3(32, 8)>>>(Wo, woh, wol, 1024, 1024);

    // Q & K projections: [4096x1024] x [1024x256]  (z selects weights/output)
    gemm_mma<<<dim3(2, 32, 2), 256, GEMM_SMEM>>>(hhi, hlo, wqh, wql, pq, wkh, wkl, pk, 1024, 256);
    // V projection: [4096x1024] x [1024x1024]
    gemm_mma<<<dim3(8, 32, 1), 256, GEMM_SMEM>>>(hhi, hlo, wvh, wvl, pv, wvh, wvl, pv, 1024, 1024);
    // Attention
    attn64<<<dim3(32, Hh, Bb), 256>>>(pq, pk, pv, po);
    // o -> bf16 hi/lo, then output projection
    split_rows<<<(BL * 1024 / 4 + 255) / 256, 256>>>(po, ohi, olo, BL * 1024 / 4);
    gemm_mma<<<dim3(8, 32, 1), 256, GEMM_SMEM>>>(ohi, olo, woh, wol, out, woh, wol, out, 1024, 1024);
}

// round 4
// speedup vs baseline: 1.9573x; 1.4403x over previous
#include <cuda_runtime.h>
#include <cuda_bf16.h>
#include <stdint.h>

// ReBasedLinearAttention: B=2, L=2048, D=1024, H=16, FD=16, HD=64
// Everything heavy on mma.sync bf16 hi/lo (3-MMA fp32 emulation).

#define Bb 2
#define Ll 2048
#define Dd 1024
#define Hh 16
#define BL (Bb * Ll)

typedef unsigned long long ull;
typedef __nv_bfloat16 bf16;

// ---------------- scratch ----------------
__device__ bf16 g_hhi[BL * 1024];
__device__ bf16 g_hlo[BL * 1024];
__device__ bf16 g_qhi[BL * 256];
__device__ bf16 g_qlo[BL * 256];
__device__ bf16 g_khi[BL * 256];
__device__ bf16 g_klo[BL * 256];
__device__ bf16 g_vhi[BL * 1024];
__device__ bf16 g_vlo[BL * 1024];
__device__ bf16 g_vthi[Bb * Hh * 64 * Ll];
__device__ bf16 g_vtlo[Bb * Hh * 64 * Ll];
__device__ bf16 g_ohi[BL * 1024];
__device__ bf16 g_olo[BL * 1024];

__device__ bf16 g_wqt_hi[256 * 1024];
__device__ bf16 g_wqt_lo[256 * 1024];
__device__ bf16 g_wkt_hi[256 * 1024];
__device__ bf16 g_wkt_lo[256 * 1024];
__device__ bf16 g_wvt_hi[1024 * 1024];
__device__ bf16 g_wvt_lo[1024 * 1024];
__device__ bf16 g_wot_hi[1024 * 1024];
__device__ bf16 g_wot_lo[1024 * 1024];

// ---------------- PTX helpers ----------------
__device__ __forceinline__ uint32_t smem_u32(const void* p) {
    uint32_t a;
    asm("{ .reg .u64 t; cvta.to.shared.u64 t, %1; cvt.u32.u64 %0, t; }" : "=r"(a) : "l"(p));
    return a;
}
__device__ __forceinline__ void cp_async16(uint32_t saddr, const void* gaddr) {
    asm volatile("cp.async.cg.shared.global [%0], [%1], 16;" :: "r"(saddr), "l"(gaddr) : "memory");
}
__device__ __forceinline__ void cp_commit() {
    asm volatile("cp.async.commit_group;" ::: "memory");
}
__device__ __forceinline__ void ldsm_x4(uint32_t& r0, uint32_t& r1, uint32_t& r2, uint32_t& r3,
                                        uint32_t addr) {
    asm volatile("ldmatrix.sync.aligned.m8n8.x4.shared.b16 {%0,%1,%2,%3}, [%4];"
                 : "=r"(r0), "=r"(r1), "=r"(r2), "=r"(r3) : "r"(addr));
}
__device__ __forceinline__ void mma16816(float c[4], uint32_t a0, uint32_t a1, uint32_t a2,
                                         uint32_t a3, uint32_t b0, uint32_t b1) {
    asm volatile(
        "mma.sync.aligned.m16n8k16.row.col.f32.bf16.bf16.f32 "
        "{%0,%1,%2,%3}, {%4,%5,%6,%7}, {%8,%9}, {%0,%1,%2,%3};"
        : "+f"(c[0]), "+f"(c[1]), "+f"(c[2]), "+f"(c[3])
        : "r"(a0), "r"(a1), "r"(a2), "r"(a3), "r"(b0), "r"(b1));
}
// pack(flo -> low half, fhi -> high half)
__device__ __forceinline__ uint32_t packbf(float flo, float fhi) {
    uint32_t r;
    asm("cvt.rn.bf16x2.f32 %0, %1, %2;" : "=r"(r) : "f"(fhi), "f"(flo));
    return r;
}
__device__ __forceinline__ float bflo(uint32_t p) { return __uint_as_float(p << 16); }
__device__ __forceinline__ float bfhi(uint32_t p) { return __uint_as_float(p & 0xffff0000u); }

// ---------------------------------------------------------------------------
// fp32 -> bf16 hi/lo split
// ---------------------------------------------------------------------------
__global__ void split_rows(const float* __restrict__ X,
                           bf16* __restrict__ hi, bf16* __restrict__ lo, int n4)
{
    int i = blockIdx.x * blockDim.x + threadIdx.x;
    if (i >= n4) return;
    float4 v = ((const float4*)X)[i];
    float vv[4] = {v.x, v.y, v.z, v.w};
    bf16 hh[4], llv[4];
#pragma unroll
    for (int j = 0; j < 4; j++) {
        bf16 h = __float2bfloat16(vv[j]);
        hh[j] = h;
        llv[j] = __float2bfloat16(vv[j] - __bfloat162float(h));
    }
    *(ull*)&hi[i * 4] = *(ull*)hh;
    *(ull*)&lo[i * 4] = *(ull*)llv;
}

// ---------------------------------------------------------------------------
// W [K,N] fp32 -> Wt hi/lo [N,K] bf16
// ---------------------------------------------------------------------------
__global__ void transpose_split(const float* __restrict__ W,
                                bf16* __restrict__ thi, bf16* __restrict__ tlo, int K, int N)
{
    __shared__ float t[32][33];
    int n0 = blockIdx.x * 32, k0 = blockIdx.y * 32;
    int tx = threadIdx.x, ty = threadIdx.y;
#pragma unroll
    for (int i = 0; i < 4; i++)
        t[ty + i * 8][tx] = W[(size_t)(k0 + ty + i * 8) * N + n0 + tx];
    __syncthreads();
#pragma unroll
    for (int i = 0; i < 4; i++) {
        int r = ty + i * 8;
        float v = t[tx][r];
        bf16 h = __float2bfloat16(v);
        bf16 l = __float2bfloat16(v - __bfloat162float(h));
        thi[(size_t)(n0 + r) * K + k0 + tx] = h;
        tlo[(size_t)(n0 + r) * K + k0 + tx] = l;
    }
}

// ---------------------------------------------------------------------------
// v [BL][h*64+d] hi/lo -> vt [(b*16+h)*64+d][L] hi/lo
// ---------------------------------------------------------------------------
__global__ void transpose_v(const bf16* __restrict__ vhi, const bf16* __restrict__ vlo,
                            bf16* __restrict__ vthi, bf16* __restrict__ vtlo)
{
    __shared__ bf16 t[2][64][72];
    const int l0 = blockIdx.x * 64;
    const int h = blockIdx.y;
    const int b = blockIdx.z;
    const int tid = threadIdx.x;
#pragma unroll
    for (int tt = 0; tt < 4; tt++) {
        int idx = tt * 256 + tid;
        int arr = idx >> 9;
        int rem = idx & 511;
        int row = rem >> 3;      // l offset
        int ch = rem & 7;        // d chunk (8 bf16)
        const bf16* src = arr ? vlo : vhi;
        uint4 val = *(const uint4*)&src[(size_t)(b * Ll + l0 + row) * 1024 + h * 64 + ch * 8];
        bf16 tmp[8];
        *(uint4*)tmp = val;
#pragma unroll
        for (int j = 0; j < 8; j++) t[arr][ch * 8 + j][row] = tmp[j];
    }
    __syncthreads();
#pragma unroll
    for (int tt = 0; tt < 4; tt++) {
        int idx = tt * 256 + tid;
        int arr = idx >> 9;
        int rem = idx & 511;
        int d = rem >> 3;
        int lc = rem & 7;        // l chunk (8 bf16)
        bf16* dst = arr ? vtlo : vthi;
        uint4 val = *(const uint4*)&t[arr][d][lc * 8];
        *(uint4*)&dst[(size_t)((b * Hh + h) * 64 + d) * Ll + l0 + lc * 8] = val;
    }
}

// ---------------------------------------------------------------------------
// bf16x3 GEMM via mma.sync: C[M,N] = A[M,K] @ Bt[N,K]^T
// OUT=0: fp32 C.  OUT=1: bf16 hi/lo C.
// ---------------------------------------------------------------------------
#define ROWB 80
#define MATB (128 * ROWB)
#define STAGEB (4 * MATB)
#define GEMM_SMEM (2 * STAGEB)

template <int OUT>
__global__ __launch_bounds__(256, 1)
void gemm_mma_t(const bf16* __restrict__ Ahi, const bf16* __restrict__ Alo,
                const bf16* __restrict__ Bhi0, const bf16* __restrict__ Blo0,
                float* __restrict__ C0, bf16* __restrict__ Chi0, bf16* __restrict__ Clo0,
                const bf16* __restrict__ Bhi1, const bf16* __restrict__ Blo1,
                float* __restrict__ C1, bf16* __restrict__ Chi1, bf16* __restrict__ Clo1,
                int Ktot, int N)
{
    const bf16* __restrict__ Bhi = (blockIdx.z == 0) ? Bhi0 : Bhi1;
    const bf16* __restrict__ Blo = (blockIdx.z == 0) ? Blo0 : Blo1;
    float* __restrict__ C = (blockIdx.z == 0) ? C0 : C1;
    bf16* __restrict__ Chi = (blockIdx.z == 0) ? Chi0 : Chi1;
    bf16* __restrict__ Clo = (blockIdx.z == 0) ? Clo0 : Clo1;

    extern __shared__ char smem_raw[];
    const uint32_t sbase = smem_u32(smem_raw);

    const int tid = threadIdx.x;
    const int lane = tid & 31;
    const int warp = tid >> 5;
    const int wm = warp >> 2;
    const int wn = warp & 3;
    const int rowBase = blockIdx.y * 128;
    const int colBase = blockIdx.x * 128;
    const int S = Ktot / 32;

    float acc[4][4][4];
#pragma unroll
    for (int i = 0; i < 4; i++)
#pragma unroll
        for (int j = 0; j < 4; j++)
#pragma unroll
            for (int e = 0; e < 4; e++) acc[i][j][e] = 0.f;

    const int lrow = lane & 15;
    const int lkb = ((lane >> 4) & 1) * 16;

#define LOAD_STAGE(s, buf)                                                              \
    do {                                                                                \
        const int k0 = (s) * 32;                                                        \
        const uint32_t sb_ = sbase + (buf) * STAGEB;                                    \
        _Pragma("unroll")                                                               \
        for (int t = 0; t < 8; t++) {                                                   \
            int mat = t >> 1;                                                           \
            int sub = (t & 1) * 256 + tid;                                              \
            int row = sub >> 2;                                                         \
            int kc = sub & 3;                                                           \
            const bf16* src = (mat == 0) ? Ahi : (mat == 1) ? Alo                       \
                             : (mat == 2) ? Bhi : Blo;                                  \
            int grow = ((mat < 2) ? rowBase : colBase) + row;                           \
            const bf16* g = src + (size_t)grow * Ktot + k0 + kc * 8;                    \
            uint32_t sa = sb_ + mat * MATB + row * ROWB + kc * 16;                      \
            cp_async16(sa, g);                                                          \
        }                                                                               \
        cp_commit();                                                                    \
    } while (0)

    LOAD_STAGE(0, 0);

    for (int s = 0; s < S; s++) {
        if (s + 1 < S) {
            LOAD_STAGE(s + 1, (s + 1) & 1);
            asm volatile("cp.async.wait_group 1;" ::: "memory");
        } else {
            asm volatile("cp.async.wait_group 0;" ::: "memory");
        }
        __syncthreads();

        const uint32_t sb = sbase + (s & 1) * STAGEB;
#pragma unroll
        for (int s2 = 0; s2 < 2; s2++) {
            const uint32_t kbyte = s2 * 32 + lkb;

            uint32_t Ah[4][4], Al[4][4];
#pragma unroll
            for (int mf = 0; mf < 4; mf++) {
                uint32_t ra = sb + (uint32_t)((wm * 64 + mf * 16 + lrow) * ROWB) + kbyte;
                ldsm_x4(Ah[mf][0], Ah[mf][1], Ah[mf][2], Ah[mf][3], ra);
                ldsm_x4(Al[mf][0], Al[mf][1], Al[mf][2], Al[mf][3], ra + MATB);
            }
            uint32_t Bh[4][2], Blr[4][2];
#pragma unroll
            for (int nf2 = 0; nf2 < 2; nf2++) {
                uint32_t rb = sb + 2 * MATB +
                              (uint32_t)((wn * 32 + nf2 * 16 + lrow) * ROWB) + kbyte;
                uint32_t q0, q1, q2, q3;
                ldsm_x4(q0, q1, q2, q3, rb);
                Bh[nf2 * 2 + 0][0] = q0; Bh[nf2 * 2 + 0][1] = q2;
                Bh[nf2 * 2 + 1][0] = q1; Bh[nf2 * 2 + 1][1] = q3;
                ldsm_x4(q0, q1, q2, q3, rb + MATB);
                Blr[nf2 * 2 + 0][0] = q0; Blr[nf2 * 2 + 0][1] = q2;
                Blr[nf2 * 2 + 1][0] = q1; Blr[nf2 * 2 + 1][1] = q3;
            }

#pragma unroll
            for (int mf = 0; mf < 4; mf++)
#pragma unroll
                for (int nf = 0; nf < 4; nf++) {
                    mma16816(acc[mf][nf], Ah[mf][0], Ah[mf][1], Ah[mf][2], Ah[mf][3],
                             Bh[nf][0], Bh[nf][1]);
                    mma16816(acc[mf][nf], Ah[mf][0], Ah[mf][1], Ah[mf][2], Ah[mf][3],
                             Blr[nf][0], Blr[nf][1]);
                    mma16816(acc[mf][nf], Al[mf][0], Al[mf][1], Al[mf][2], Al[mf][3],
                             Bh[nf][0], Bh[nf][1]);
                }
        }
        __syncthreads();
    }

    const int r0b = rowBase + wm * 64 + (lane >> 2);
    const int c0b = colBase + wn * 32 + (lane & 3) * 2;
#pragma unroll
    for (int mf = 0; mf < 4; mf++) {
#pragma unroll
        for (int nf = 0; nf < 4; nf++) {
            int r = r0b + mf * 16;
            int c = c0b + nf * 8;
            if (OUT == 0) {
                *(float2*)&C[(size_t)r * N + c] = make_float2(acc[mf][nf][0], acc[mf][nf][1]);
                *(float2*)&C[(size_t)(r + 8) * N + c] = make_float2(acc[mf][nf][2], acc[mf][nf][3]);
            } else {
                uint32_t h01 = packbf(acc[mf][nf][0], acc[mf][nf][1]);
                uint32_t h23 = packbf(acc[mf][nf][2], acc[mf][nf][3]);
                uint32_t l01 = packbf(acc[mf][nf][0] - bflo(h01), acc[mf][nf][1] - bfhi(h01));
                uint32_t l23 = packbf(acc[mf][nf][2] - bflo(h23), acc[mf][nf][3] - bfhi(h23));
                ((uint32_t*)Chi)[((size_t)r * N + c) >> 1] = h01;
                ((uint32_t*)Clo)[((size_t)r * N + c) >> 1] = l01;
                ((uint32_t*)Chi)[((size_t)(r + 8) * N + c) >> 1] = h23;
                ((uint32_t*)Clo)[((size_t)(r + 8) * N + c) >> 1] = l23;
            }
        }
    }
}

// ---------------------------------------------------------------------------
// Tensor-core rebased attention.
// CTA = (b, h, 128-query tile), 256 threads (warps: 4m x 2n).
// Key tiles of 64, cp.async double-buffered. s = (q.k)^2/16, causal.
// ---------------------------------------------------------------------------
#define SQH 0
#define SQL 6144
#define S_TILES 12288
#define A_BUFSZ 24576
// within buffer: kh +0 (3072), kl +3072, vth +6144 (9216), vtl +15360 (9216)
#define SZOFF 61440
#define ATT_SMEM 61952
#define OSM_STRIDE 66

__global__ __launch_bounds__(256, 1)
void attn_mma(const bf16* __restrict__ qhi, const bf16* __restrict__ qlo,
              const bf16* __restrict__ khi, const bf16* __restrict__ klo,
              const bf16* __restrict__ vthi, const bf16* __restrict__ vtlo,
              bf16* __restrict__ ohi, bf16* __restrict__ olo)
{
    extern __shared__ char smem_raw[];
    const uint32_t sbase = smem_u32(smem_raw);

    const int qt = 15 - (int)blockIdx.x;
    const int h = blockIdx.y;
    const int b = blockIdx.z;
    const int qi0 = qt * 128;
    const int nt = 2 * qt + 2;

    const int tid = threadIdx.x;
    const int lane = tid & 31;
    const int warp = tid >> 5;
    const int wm = warp >> 1;   // 0..3 : 32 q rows
    const int wn = warp & 1;    // 0..1 : 32 keys of each tile
    const int lrow = lane & 15;
    const int lkb = ((lane >> 4) & 1) * 16;

    // ---- load q tile (128 x 16, hi+lo) ----
#pragma unroll
    for (int t = 0; t < 2; t++) {
        int idx = t * 256 + tid;
        int arr = idx >> 8;
        int rem = idx & 255;
        int row = rem >> 1;
        int ch = rem & 1;
        const bf16* src = arr ? qlo : qhi;
        uint4 v = *(const uint4*)&src[(size_t)(b * Ll + qi0 + row) * 256 + h * 16 + ch * 8];
        *(uint4*)(smem_raw + (arr ? SQL : SQH) + row * 48 + ch * 16) = v;
    }
    __syncthreads();

    // q A-frags (persist across tiles)
    uint32_t Aqh[2][4], Aql[2][4];
#pragma unroll
    for (int mf = 0; mf < 2; mf++) {
        uint32_t ra = sbase + SQH + (uint32_t)((wm * 32 + mf * 16 + lrow) * 48) + lkb;
        ldsm_x4(Aqh[mf][0], Aqh[mf][1], Aqh[mf][2], Aqh[mf][3], ra);
        ldsm_x4(Aql[mf][0], Aql[mf][1], Aql[mf][2], Aql[mf][3], ra + (SQL - SQH));
    }

    float oacc[2][8][4];
#pragma unroll
    for (int i = 0; i < 2; i++)
#pragma unroll
        for (int j = 0; j < 8; j++)
#pragma unroll
            for (int e = 0; e < 4; e++) oacc[i][j][e] = 0.f;
    float zv[2][2] = {{0.f, 0.f}, {0.f, 0.f}};

    const size_t vtrow0 = (size_t)((b * Hh + h) * 64) * Ll;

#define ATT_LOAD(t, bsel)                                                                \
    do {                                                                                 \
        const int j0_ = (t) * 64;                                                        \
        const uint32_t bb = sbase + S_TILES + (bsel) * A_BUFSZ;                          \
        {                                                                                \
            int arr = tid >> 7;                                                          \
            int rem = tid & 127;                                                         \
            int row = rem >> 1;                                                          \
            int ch = rem & 1;                                                            \
            const bf16* src = arr ? klo : khi;                                           \
            cp_async16(bb + arr * 3072 + row * 48 + ch * 16,                             \
                       src + (size_t)(b * Ll + j0_ + row) * 256 + h * 16 + ch * 8);      \
        }                                                                                \
        _Pragma("unroll")                                                                \
        for (int t2 = 0; t2 < 4; t2++) {                                                 \
            int idx = t2 * 256 + tid;                                                    \
            int arr = idx >> 9;                                                          \
            int rem = idx & 511;                                                         \
            int row = rem >> 3;                                                          \
            int ch = rem & 7;                                                            \
            const bf16* src = arr ? vtlo : vthi;                                         \
            cp_async16(bb + 6144 + arr * 9216 + row * 144 + ch * 16,                     \
                       src + vtrow0 + (size_t)row * Ll + j0_ + ch * 8);                  \
        }                                                                                \
        cp_commit();                                                                     \
    } while (0)

    ATT_LOAD(0, 0);

    for (int t = 0; t < nt; t++) {
        if (t + 1 < nt) {
            ATT_LOAD(t + 1, (t + 1) & 1);
            asm volatile("cp.async.wait_group 1;" ::: "memory");
        } else {
            asm volatile("cp.async.wait_group 0;" ::: "memory");
        }
        __syncthreads();

        const int j0 = t * 64;
        const uint32_t bb = sbase + S_TILES + (t & 1) * A_BUFSZ;

        // ---- QK^T ----
        float sacc[2][4][4];
#pragma unroll
        for (int i = 0; i < 2; i++)
#pragma unroll
            for (int j = 0; j < 4; j++)
#pragma unroll
                for (int e = 0; e < 4; e++) sacc[i][j][e] = 0.f;

#pragma unroll
        for (int nf2 = 0; nf2 < 2; nf2++) {
            uint32_t ra = bb + (uint32_t)((wn * 32 + nf2 * 16 + lrow) * 48) + lkb;
            uint32_t kh0, kh1, kh2, kh3, kl0, kl1, kl2, kl3;
            ldsm_x4(kh0, kh1, kh2, kh3, ra);
            ldsm_x4(kl0, kl1, kl2, kl3, ra + 3072);
#pragma unroll
            for (int mf = 0; mf < 2; mf++) {
                mma16816(sacc[mf][nf2 * 2 + 0], Aqh[mf][0], Aqh[mf][1], Aqh[mf][2], Aqh[mf][3], kh0, kh2);
                mma16816(sacc[mf][nf2 * 2 + 0], Aqh[mf][0], Aqh[mf][1], Aqh[mf][2], Aqh[mf][3], kl0, kl2);
                mma16816(sacc[mf][nf2 * 2 + 0], Aql[mf][0], Aql[mf][1], Aql[mf][2], Aql[mf][3], kh0, kh2);
                mma16816(sacc[mf][nf2 * 2 + 1], Aqh[mf][0], Aqh[mf][1], Aqh[mf][2], Aqh[mf][3], kh1, kh3);
                mma16816(sacc[mf][nf2 * 2 + 1], Aqh[mf][0], Aqh[mf][1], Aqh[mf][2], Aqh[mf][3], kl1, kl3);
                mma16816(sacc[mf][nf2 * 2 + 1], Aql[mf][0], Aql[mf][1], Aql[mf][2], Aql[mf][3], kh1, kh3);
            }
        }

        // ---- square, scale, mask, z, repack to A-frags ----
        uint32_t Ash[2][2][4], Asl[2][2][4];
        const bool dm = (j0 + 64 > qi0);
        const int rq = qi0 + wm * 32 + (lane >> 2);
        const int cb0 = j0 + wn * 32 + (lane & 3) * 2;
#pragma unroll
        for (int mf = 0; mf < 2; mf++) {
            const int r0 = rq + mf * 16;
            const int r1 = r0 + 8;
#pragma unroll
            for (int nf = 0; nf < 4; nf++) {
                float* c = sacc[mf][nf];
                const int cb = cb0 + nf * 8;
                float s0 = c[0] * c[0] * 0.0625f;
                float s1 = c[1] * c[1] * 0.0625f;
                float s2 = c[2] * c[2] * 0.0625f;
                float s3 = c[3] * c[3] * 0.0625f;
                if (dm) {
                    if (cb > r0) s0 = 0.f;
                    if (cb + 1 > r0) s1 = 0.f;
                    if (cb > r1) s2 = 0.f;
                    if (cb + 1 > r1) s3 = 0.f;
                }
                zv[mf][0] += s0 + s1;
                zv[mf][1] += s2 + s3;
                uint32_t h01 = packbf(s0, s1);
                uint32_t h23 = packbf(s2, s3);
                uint32_t l01 = packbf(s0 - bflo(h01), s1 - bfhi(h01));
                uint32_t l23 = packbf(s2 - bflo(h23), s3 - bfhi(h23));
                int kc = nf >> 1, nfs = nf & 1;
                Ash[mf][kc][nfs * 2 + 0] = h01;
                Ash[mf][kc][nfs * 2 + 1] = h23;
                Asl[mf][kc][nfs * 2 + 0] = l01;
                Asl[mf][kc][nfs * 2 + 1] = l23;
            }
        }

        // ---- SV: o += s @ v ----
#pragma unroll
        for (int kc = 0; kc < 2; kc++) {
#pragma unroll
            for (int nf2 = 0; nf2 < 4; nf2++) {
                uint32_t av = bb + 6144 + (uint32_t)((nf2 * 16 + lrow) * 144) +
                              (uint32_t)(wn * 64 + kc * 32) + lkb;
                uint32_t vh0, vh1, vh2, vh3, vl0, vl1, vl2, vl3;
                ldsm_x4(vh0, vh1, vh2, vh3, av);
                ldsm_x4(vl0, vl1, vl2, vl3, av + 9216);
#pragma unroll
                for (int mf = 0; mf < 2; mf++) {
                    mma16816(oacc[mf][nf2 * 2 + 0], Ash[mf][kc][0], Ash[mf][kc][1], Ash[mf][kc][2], Ash[mf][kc][3], vh0, vh2);
                    mma16816(oacc[mf][nf2 * 2 + 0], Ash[mf][kc][0], Ash[mf][kc][1], Ash[mf][kc][2], Ash[mf][kc][3], vl0, vl2);
                    mma16816(oacc[mf][nf2 * 2 + 0], Asl[mf][kc][0], Asl[mf][kc][1], Asl[mf][kc][2], Asl[mf][kc][3], vh0, vh2);
                    mma16816(oacc[mf][nf2 * 2 + 1], Ash[mf][kc][0], Ash[mf][kc][1], Ash[mf][kc][2], Ash[mf][kc][3], vh1, vh3);
                    mma16816(oacc[mf][nf2 * 2 + 1], Ash[mf][kc][0], Ash[mf][kc][1], Ash[mf][kc][2], Ash[mf][kc][3], vl1, vl3);
                    mma16816(oacc[mf][nf2 * 2 + 1], Asl[mf][kc][0], Asl[mf][kc][1], Asl[mf][kc][2], Asl[mf][kc][3], vh1, vh3);
                }
            }
        }
        __syncthreads();
    }

    // ---- epilogue: reduce z over quad, exchange across n-warps, write o hi/lo ----
#pragma unroll
    for (int mf = 0; mf < 2; mf++)
#pragma unroll
        for (int hf = 0; hf < 2; hf++) {
            zv[mf][hf] += __shfl_xor_sync(0xffffffffu, zv[mf][hf], 1);
            zv[mf][hf] += __shfl_xor_sync(0xffffffffu, zv[mf][hf], 2);
        }

    float* osm = (float*)smem_raw;
    float* zsm = (float*)(smem_raw + SZOFF);

    if (wn == 0) {
#pragma unroll
        for (int mf = 0; mf < 2; mf++) {
            int r0 = wm * 32 + mf * 16 + (lane >> 2);
#pragma unroll
            for (int nf = 0; nf < 8; nf++) {
                int col = nf * 8 + (lane & 3) * 2;
                *(float2*)&osm[r0 * OSM_STRIDE + col] = make_float2(oacc[mf][nf][0], oacc[mf][nf][1]);
                *(float2*)&osm[(r0 + 8) * OSM_STRIDE + col] = make_float2(oacc[mf][nf][2], oacc[mf][nf][3]);
            }
            if ((lane & 3) == 0) {
                zsm[r0] = zv[mf][0];
                zsm[r0 + 8] = zv[mf][1];
            }
        }
    }
    __syncthreads();
    if (wn == 1) {
#pragma unroll
        for (int mf = 0; mf < 2; mf++) {
            int r0 = wm * 32 + mf * 16 + (lane >> 2);
            float inv0 = 1.f / (zv[mf][0] + zsm[r0] + 1e-5f);
            float inv1 = 1.f / (zv[mf][1] + zsm[r0 + 8] + 1e-5f);
            size_t g0 = (size_t)(b * Ll + qi0 + r0) * 1024 + h * 64;
            size_t g1 = (size_t)(b * Ll + qi0 + r0 + 8) * 1024 + h * 64;
#pragma unroll
            for (int nf = 0; nf < 8; nf++) {
                int col = nf * 8 + (lane & 3) * 2;
                float f0 = (oacc[mf][nf][0] + osm[r0 * OSM_STRIDE + col]) * inv0;
                float f1 = (oacc[mf][nf][1] + osm[r0 * OSM_STRIDE + col + 1]) * inv0;
                float f2 = (oacc[mf][nf][2] + osm[(r0 + 8) * OSM_STRIDE + col]) * inv1;
                float f3 = (oacc[mf][nf][3] + osm[(r0 + 8) * OSM_STRIDE + col + 1]) * inv1;
                uint32_t h01 = packbf(f0, f1);
                uint32_t h23 = packbf(f2, f3);
                uint32_t l01 = packbf(f0 - bflo(h01), f1 - bfhi(h01));
                uint32_t l23 = packbf(f2 - bflo(h23), f3 - bfhi(h23));
                ((uint32_t*)ohi)[(g0 + col) >> 1] = h01;
                ((uint32_t*)olo)[(g0 + col) >> 1] = l01;
                ((uint32_t*)ohi)[(g1 + col) >> 1] = h23;
                ((uint32_t*)olo)[(g1 + col) >> 1] = l23;
            }
        }
    }
}

// ---------------------------------------------------------------------------
extern "C" void kernel_launch(void* const* d_in, const int* in_sizes, int n_in,
                              void* d_out, int out_size)
{
    const float* hidden = (const float*)d_in[0];
    const float* Wq = (const float*)d_in[1];
    const float* Wk = (const float*)d_in[2];
    const float* Wv = (const float*)d_in[3];
    const float* Wo = (const float*)d_in[4];
    float* out = (float*)d_out;

    bf16 *hhi, *hlo, *qhi, *qlo, *khi, *klo, *vhi, *vlo, *vthi, *vtlo, *ohi, *olo;
    cudaGetSymbolAddress((void**)&hhi, g_hhi);
    cudaGetSymbolAddress((void**)&hlo, g_hlo);
    cudaGetSymbolAddress((void**)&qhi, g_qhi);
    cudaGetSymbolAddress((void**)&qlo, g_qlo);
    cudaGetSymbolAddress((void**)&khi, g_khi);
    cudaGetSymbolAddress((void**)&klo, g_klo);
    cudaGetSymbolAddress((void**)&vhi, g_vhi);
    cudaGetSymbolAddress((void**)&vlo, g_vlo);
    cudaGetSymbolAddress((void**)&vthi, g_vthi);
    cudaGetSymbolAddress((void**)&vtlo, g_vtlo);
    cudaGetSymbolAddress((void**)&ohi, g_ohi);
    cudaGetSymbolAddress((void**)&olo, g_olo);
    bf16 *wqh, *wql, *wkh, *wkl, *wvh, *wvl, *woh, *wol;
    cudaGetSymbolAddress((void**)&wqh, g_wqt_hi);
    cudaGetSymbolAddress((void**)&wql, g_wqt_lo);
    cudaGetSymbolAddress((void**)&wkh, g_wkt_hi);
    cudaGetSymbolAddress((void**)&wkl, g_wkt_lo);
    cudaGetSymbolAddress((void**)&wvh, g_wvt_hi);
    cudaGetSymbolAddress((void**)&wvl, g_wvt_lo);
    cudaGetSymbolAddress((void**)&woh, g_wot_hi);
    cudaGetSymbolAddress((void**)&wol, g_wot_lo);

    cudaFuncSetAttribute(gemm_mma_t<0>, cudaFuncAttributeMaxDynamicSharedMemorySize, GEMM_SMEM);
    cudaFuncSetAttribute(gemm_mma_t<1>, cudaFuncAttributeMaxDynamicSharedMemorySize, GEMM_SMEM);
    cudaFuncSetAttribute(attn_mma, cudaFuncAttributeMaxDynamicSharedMemorySize, ATT_SMEM);

    // conversions
    split_rows<<<(BL * 1024 / 4 + 255) / 256, 256>>>(hidden, hhi, hlo, BL * 1024 / 4);
    transpose_split<<<dim3(8, 32), dim3(32, 8)>>>(Wq, wqh, wql, 1024, 256);
    transpose_split<<<dim3(8, 32), dim3(32, 8)>>>(Wk, wkh, wkl, 1024, 256);
    transpose_split<<<dim3(32, 32), dim3(32, 8)>>>(Wv, wvh, wvl, 1024, 1024);
    transpose_split<<<dim3(32, 32), dim3(32, 8)>>>(Wo, woh, wol, 1024, 1024);

    // Q & K projections -> bf16 hi/lo
    gemm_mma_t<1><<<dim3(2, 32, 2), 256, GEMM_SMEM>>>(
        hhi, hlo, wqh, wql, nullptr, qhi, qlo, wkh, wkl, nullptr, khi, klo, 1024, 256);
    // V projection -> bf16 hi/lo
    gemm_mma_t<1><<<dim3(8, 32, 1), 256, GEMM_SMEM>>>(
        hhi, hlo, wvh, wvl, nullptr, vhi, vlo, wvh, wvl, nullptr, vhi, vlo, 1024, 1024);
    // v -> vt
    transpose_v<<<dim3(32, 16, 2), 256>>>(vhi, vlo, vthi, vtlo);
    // attention -> o hi/lo
    attn_mma<<<dim3(16, Hh, Bb), 256, ATT_SMEM>>>(qhi, qlo, khi, klo, vthi, vtlo, ohi, olo);
    // output projection (fp32 out)
    gemm_mma_t<0><<<dim3(8, 32, 1), 256, GEMM_SMEM>>>(
        ohi, olo, woh, wol, out, nullptr, nullptr, woh, wol, out, nullptr, nullptr, 1024, 1024);
}

// round 5
// speedup vs baseline: 2.0940x; 1.0699x over previous
#include <cuda_runtime.h>
#include <cuda_bf16.h>
#include <stdint.h>

// ReBasedLinearAttention: B=2, L=2048, D=1024, H=16, FD=16, HD=64
// All heavy math on mma.sync bf16 hi/lo (3-MMA fp32 emulation).

#define Bb 2
#define Ll 2048
#define Dd 1024
#define Hh 16
#define BL (Bb * Ll)

typedef unsigned long long ull;
typedef __nv_bfloat16 bf16;

// ---------------- scratch ----------------
__device__ bf16 g_hhi[BL * 1024];
__device__ bf16 g_hlo[BL * 1024];
__device__ bf16 g_qhi[BL * 256];
__device__ bf16 g_qlo[BL * 256];
__device__ bf16 g_khi[BL * 256];
__device__ bf16 g_klo[BL * 256];
__device__ bf16 g_vhi[BL * 1024];
__device__ bf16 g_vlo[BL * 1024];
__device__ bf16 g_ohi[BL * 1024];
__device__ bf16 g_olo[BL * 1024];

__device__ bf16 g_wqt_hi[256 * 1024];
__device__ bf16 g_wqt_lo[256 * 1024];
__device__ bf16 g_wkt_hi[256 * 1024];
__device__ bf16 g_wkt_lo[256 * 1024];
__device__ bf16 g_wvt_hi[1024 * 1024];
__device__ bf16 g_wvt_lo[1024 * 1024];
__device__ bf16 g_wot_hi[1024 * 1024];
__device__ bf16 g_wot_lo[1024 * 1024];

// ---------------- PTX helpers ----------------
__device__ __forceinline__ uint32_t smem_u32(const void* p) {
    uint32_t a;
    asm("{ .reg .u64 t; cvta.to.shared.u64 t, %1; cvt.u32.u64 %0, t; }" : "=r"(a) : "l"(p));
    return a;
}
__device__ __forceinline__ void cp_async16(uint32_t saddr, const void* gaddr) {
    asm volatile("cp.async.cg.shared.global [%0], [%1], 16;" :: "r"(saddr), "l"(gaddr) : "memory");
}
__device__ __forceinline__ void cp_commit() {
    asm volatile("cp.async.commit_group;" ::: "memory");
}
__device__ __forceinline__ void ldsm_x4(uint32_t& r0, uint32_t& r1, uint32_t& r2, uint32_t& r3,
                                        uint32_t addr) {
    asm volatile("ldmatrix.sync.aligned.m8n8.x4.shared.b16 {%0,%1,%2,%3}, [%4];"
                 : "=r"(r0), "=r"(r1), "=r"(r2), "=r"(r3) : "r"(addr));
}
__device__ __forceinline__ void ldsm_x4_t(uint32_t& r0, uint32_t& r1, uint32_t& r2, uint32_t& r3,
                                          uint32_t addr) {
    asm volatile("ldmatrix.sync.aligned.m8n8.x4.trans.shared.b16 {%0,%1,%2,%3}, [%4];"
                 : "=r"(r0), "=r"(r1), "=r"(r2), "=r"(r3) : "r"(addr));
}
__device__ __forceinline__ void mma16816(float c[4], uint32_t a0, uint32_t a1, uint32_t a2,
                                         uint32_t a3, uint32_t b0, uint32_t b1) {
    asm volatile(
        "mma.sync.aligned.m16n8k16.row.col.f32.bf16.bf16.f32 "
        "{%0,%1,%2,%3}, {%4,%5,%6,%7}, {%8,%9}, {%0,%1,%2,%3};"
        : "+f"(c[0]), "+f"(c[1]), "+f"(c[2]), "+f"(c[3])
        : "r"(a0), "r"(a1), "r"(a2), "r"(a3), "r"(b0), "r"(b1));
}
__device__ __forceinline__ uint32_t packbf(float flo, float fhi) {
    uint32_t r;
    asm("cvt.rn.bf16x2.f32 %0, %1, %2;" : "=r"(r) : "f"(fhi), "f"(flo));
    return r;
}
__device__ __forceinline__ float bflo(uint32_t p) { return __uint_as_float(p << 16); }
__device__ __forceinline__ float bfhi(uint32_t p) { return __uint_as_float(p & 0xffff0000u); }

// ---------------------------------------------------------------------------
// fp32 -> bf16 hi/lo split
// ---------------------------------------------------------------------------
__global__ void split_rows(const float* __restrict__ X,
                           bf16* __restrict__ hi, bf16* __restrict__ lo, int n4)
{
    int i = blockIdx.x * blockDim.x + threadIdx.x;
    if (i >= n4) return;
    float4 v = ((const float4*)X)[i];
    float vv[4] = {v.x, v.y, v.z, v.w};
    bf16 hh[4], llv[4];
#pragma unroll
    for (int j = 0; j < 4; j++) {
        bf16 h = __float2bfloat16(vv[j]);
        hh[j] = h;
        llv[j] = __float2bfloat16(vv[j] - __bfloat162float(h));
    }
    *(ull*)&hi[i * 4] = *(ull*)hh;
    *(ull*)&lo[i * 4] = *(ull*)llv;
}

// ---------------------------------------------------------------------------
// W [K,N] fp32 -> Wt hi/lo [N,K] bf16
// ---------------------------------------------------------------------------
__global__ void transpose_split(const float* __restrict__ W,
                                bf16* __restrict__ thi, bf16* __restrict__ tlo, int K, int N)
{
    __shared__ float t[32][33];
    int n0 = blockIdx.x * 32, k0 = blockIdx.y * 32;
    int tx = threadIdx.x, ty = threadIdx.y;
#pragma unroll
    for (int i = 0; i < 4; i++)
        t[ty + i * 8][tx] = W[(size_t)(k0 + ty + i * 8) * N + n0 + tx];
    __syncthreads();
#pragma unroll
    for (int i = 0; i < 4; i++) {
        int r = ty + i * 8;
        float v = t[tx][r];
        bf16 h = __float2bfloat16(v);
        bf16 l = __float2bfloat16(v - __bfloat162float(h));
        thi[(size_t)(n0 + r) * K + k0 + tx] = h;
        tlo[(size_t)(n0 + r) * K + k0 + tx] = l;
    }
}

// ---------------------------------------------------------------------------
// GEMM core macros (shared by qkv-projection kernel and O-projection kernel)
// ---------------------------------------------------------------------------
#define ROWB 80
#define MATB (128 * ROWB)
#define STAGEB (4 * MATB)
#define GEMM_SMEM (2 * STAGEB)

#define LOAD_STAGE(s, buf)                                                              \
    do {                                                                                \
        const int k0 = (s) * 32;                                                        \
        const uint32_t sb_ = sbase + (buf) * STAGEB;                                    \
        _Pragma("unroll")                                                               \
        for (int t = 0; t < 8; t++) {                                                   \
            int mat = t >> 1;                                                           \
            int sub = (t & 1) * 256 + tid;                                              \
            int row = sub >> 2;                                                         \
            int kc = sub & 3;                                                           \
            const bf16* src = (mat == 0) ? Ahi : (mat == 1) ? Alo                       \
                             : (mat == 2) ? Bhi : Blo;                                  \
            int grow = ((mat < 2) ? rowBase : colBase) + row;                           \
            const bf16* g = src + (size_t)grow * 1024 + k0 + kc * 8;                    \
            uint32_t sa = sb_ + mat * MATB + row * ROWB + kc * 16;                      \
            cp_async16(sa, g);                                                          \
        }                                                                               \
        cp_commit();                                                                    \
    } while (0)

#define GEMM_MAINLOOP()                                                                 \
    LOAD_STAGE(0, 0);                                                                   \
    for (int s = 0; s < 32; s++) {                                                      \
        if (s + 1 < 32) {                                                               \
            LOAD_STAGE(s + 1, (s + 1) & 1);                                             \
            asm volatile("cp.async.wait_group 1;" ::: "memory");                        \
        } else {                                                                        \
            asm volatile("cp.async.wait_group 0;" ::: "memory");                        \
        }                                                                               \
        __syncthreads();                                                                \
        const uint32_t sb = sbase + (s & 1) * STAGEB;                                   \
        _Pragma("unroll")                                                               \
        for (int s2 = 0; s2 < 2; s2++) {                                                \
            const uint32_t kbyte = s2 * 32 + lkb;                                       \
            uint32_t Ah[4][4], Al[4][4];                                                \
            _Pragma("unroll")                                                           \
            for (int mf = 0; mf < 4; mf++) {                                            \
                uint32_t ra = sb + (uint32_t)((wm * 64 + mf * 16 + lrow) * ROWB) + kbyte; \
                ldsm_x4(Ah[mf][0], Ah[mf][1], Ah[mf][2], Ah[mf][3], ra);                \
                ldsm_x4(Al[mf][0], Al[mf][1], Al[mf][2], Al[mf][3], ra + MATB);         \
            }                                                                           \
            uint32_t Bh[4][2], Blr[4][2];                                               \
            _Pragma("unroll")                                                           \
            for (int nf2 = 0; nf2 < 2; nf2++) {                                         \
                uint32_t rb = sb + 2 * MATB +                                           \
                              (uint32_t)((wn * 32 + nf2 * 16 + lrow) * ROWB) + kbyte;   \
                uint32_t q0, q1, q2, q3;                                                \
                ldsm_x4(q0, q1, q2, q3, rb);                                            \
                Bh[nf2 * 2 + 0][0] = q0; Bh[nf2 * 2 + 0][1] = q2;                       \
                Bh[nf2 * 2 + 1][0] = q1; Bh[nf2 * 2 + 1][1] = q3;                       \
                ldsm_x4(q0, q1, q2, q3, rb + MATB);                                     \
                Blr[nf2 * 2 + 0][0] = q0; Blr[nf2 * 2 + 0][1] = q2;                     \
                Blr[nf2 * 2 + 1][0] = q1; Blr[nf2 * 2 + 1][1] = q3;                     \
            }                                                                           \
            _Pragma("unroll")                                                           \
            for (int mf = 0; mf < 4; mf++)                                              \
                _Pragma("unroll")                                                       \
                for (int nf = 0; nf < 4; nf++) {                                        \
                    mma16816(acc[mf][nf], Ah[mf][0], Ah[mf][1], Ah[mf][2], Ah[mf][3],   \
                             Bh[nf][0], Bh[nf][1]);                                     \
                    mma16816(acc[mf][nf], Ah[mf][0], Ah[mf][1], Ah[mf][2], Ah[mf][3],   \
                             Blr[nf][0], Blr[nf][1]);                                   \
                    mma16816(acc[mf][nf], Al[mf][0], Al[mf][1], Al[mf][2], Al[mf][3],   \
                             Bh[nf][0], Bh[nf][1]);                                     \
                }                                                                       \
        }                                                                               \
        __syncthreads();                                                                \
    }

// ---------------------------------------------------------------------------
// QKV projection: one flat-grid launch.  tiles: [0,64) Q, [64,128) K, [128,384) V
// C written as bf16 hi/lo.
// ---------------------------------------------------------------------------
__global__ __launch_bounds__(256, 2)
void gemm_qkv(const bf16* __restrict__ Ahi, const bf16* __restrict__ Alo,
              const bf16* __restrict__ qwh, const bf16* __restrict__ qwl,
              const bf16* __restrict__ kwh, const bf16* __restrict__ kwl,
              const bf16* __restrict__ vwh, const bf16* __restrict__ vwl,
              bf16* __restrict__ qh, bf16* __restrict__ ql,
              bf16* __restrict__ kh, bf16* __restrict__ kl,
              bf16* __restrict__ vh, bf16* __restrict__ vl)
{
    int t = blockIdx.x;
    const bf16 *Bhi, *Blo;
    bf16 *Chi, *Clo;
    int N, bx, by;
    if (t < 64) {
        Bhi = qwh; Blo = qwl; Chi = qh; Clo = ql; N = 256;
        bx = t & 1; by = t >> 1;
    } else if (t < 128) {
        t -= 64;
        Bhi = kwh; Blo = kwl; Chi = kh; Clo = kl; N = 256;
        bx = t & 1; by = t >> 1;
    } else {
        t -= 128;
        Bhi = vwh; Blo = vwl; Chi = vh; Clo = vl; N = 1024;
        bx = t & 7; by = t >> 3;
    }

    extern __shared__ char smem_raw[];
    const uint32_t sbase = smem_u32(smem_raw);

    const int tid = threadIdx.x;
    const int lane = tid & 31;
    const int warp = tid >> 5;
    const int wm = warp >> 2;
    const int wn = warp & 3;
    const int rowBase = by * 128;
    const int colBase = bx * 128;

    float acc[4][4][4];
#pragma unroll
    for (int i = 0; i < 4; i++)
#pragma unroll
        for (int j = 0; j < 4; j++)
#pragma unroll
            for (int e = 0; e < 4; e++) acc[i][j][e] = 0.f;

    const int lrow = lane & 15;
    const int lkb = ((lane >> 4) & 1) * 16;

    GEMM_MAINLOOP();

    const int r0b = rowBase + wm * 64 + (lane >> 2);
    const int c0b = colBase + wn * 32 + (lane & 3) * 2;
#pragma unroll
    for (int mf = 0; mf < 4; mf++) {
#pragma unroll
        for (int nf = 0; nf < 4; nf++) {
            int r = r0b + mf * 16;
            int c = c0b + nf * 8;
            uint32_t h01 = packbf(acc[mf][nf][0], acc[mf][nf][1]);
            uint32_t h23 = packbf(acc[mf][nf][2], acc[mf][nf][3]);
            uint32_t l01 = packbf(acc[mf][nf][0] - bflo(h01), acc[mf][nf][1] - bfhi(h01));
            uint32_t l23 = packbf(acc[mf][nf][2] - bflo(h23), acc[mf][nf][3] - bfhi(h23));
            ((uint32_t*)Chi)[((size_t)r * N + c) >> 1] = h01;
            ((uint32_t*)Clo)[((size_t)r * N + c) >> 1] = l01;
            ((uint32_t*)Chi)[((size_t)(r + 8) * N + c) >> 1] = h23;
            ((uint32_t*)Clo)[((size_t)(r + 8) * N + c) >> 1] = l23;
        }
    }
}

// ---------------------------------------------------------------------------
// O projection: fp32 output.
// ---------------------------------------------------------------------------
__global__ __launch_bounds__(256, 2)
void gemm_out(const bf16* __restrict__ Ahi, const bf16* __restrict__ Alo,
              const bf16* __restrict__ Bhi, const bf16* __restrict__ Blo,
              float* __restrict__ C)
{
    extern __shared__ char smem_raw[];
    const uint32_t sbase = smem_u32(smem_raw);

    const int tid = threadIdx.x;
    const int lane = tid & 31;
    const int warp = tid >> 5;
    const int wm = warp >> 2;
    const int wn = warp & 3;
    const int rowBase = blockIdx.y * 128;
    const int colBase = blockIdx.x * 128;
    const int N = 1024;

    float acc[4][4][4];
#pragma unroll
    for (int i = 0; i < 4; i++)
#pragma unroll
        for (int j = 0; j < 4; j++)
#pragma unroll
            for (int e = 0; e < 4; e++) acc[i][j][e] = 0.f;

    const int lrow = lane & 15;
    const int lkb = ((lane >> 4) & 1) * 16;

    GEMM_MAINLOOP();

    const int r0b = rowBase + wm * 64 + (lane >> 2);
    const int c0b = colBase + wn * 32 + (lane & 3) * 2;
#pragma unroll
    for (int mf = 0; mf < 4; mf++) {
#pragma unroll
        for (int nf = 0; nf < 4; nf++) {
            int r = r0b + mf * 16;
            int c = c0b + nf * 8;
            *(float2*)&C[(size_t)r * N + c] = make_float2(acc[mf][nf][0], acc[mf][nf][1]);
            *(float2*)&C[(size_t)(r + 8) * N + c] = make_float2(acc[mf][nf][2], acc[mf][nf][3]);
        }
    }
}

// ---------------------------------------------------------------------------
// Tensor-core rebased attention.
// CTA = (b, h, 128-query tile), 256 threads (warps: 4m x 2n).
// 64-key tiles, cp.async double-buffered; v loaded in natural [key][d] layout,
// SV B-frags via ldmatrix.trans.
// ---------------------------------------------------------------------------
#define SQH 0
#define SQL 6144
#define S_TILES 12288
#define A_BUFSZ 24576
// buffer layout: kh +0 (3072), kl +3072, vh +6144 (9216), vl +15360 (9216)
#define SZOFF 61440
#define ATT_SMEM 61952
#define OSM_STRIDE 66

__global__ __launch_bounds__(256, 2)
void attn_mma(const bf16* __restrict__ qhi, const bf16* __restrict__ qlo,
              const bf16* __restrict__ khi, const bf16* __restrict__ klo,
              const bf16* __restrict__ vhi, const bf16* __restrict__ vlo,
              bf16* __restrict__ ohi, bf16* __restrict__ olo)
{
    extern __shared__ char smem_raw[];
    const uint32_t sbase = smem_u32(smem_raw);

    const int qt = 15 - (int)blockIdx.x;
    const int h = blockIdx.y;
    const int b = blockIdx.z;
    const int qi0 = qt * 128;
    const int nt = 2 * qt + 2;

    const int tid = threadIdx.x;
    const int lane = tid & 31;
    const int warp = tid >> 5;
    const int wm = warp >> 1;   // 0..3 : 32 q rows
    const int wn = warp & 1;    // 0..1 : 32 keys of each tile
    const int lrow = lane & 15;
    const int lkb = ((lane >> 4) & 1) * 16;

    // ---- load q tile (128 x 16, hi+lo) ----
#pragma unroll
    for (int t = 0; t < 2; t++) {
        int idx = t * 256 + tid;
        int arr = idx >> 8;
        int rem = idx & 255;
        int row = rem >> 1;
        int ch = rem & 1;
        const bf16* src = arr ? qlo : qhi;
        uint4 v = *(const uint4*)&src[(size_t)(b * Ll + qi0 + row) * 256 + h * 16 + ch * 8];
        *(uint4*)(smem_raw + (arr ? SQL : SQH) + row * 48 + ch * 16) = v;
    }
    __syncthreads();

    uint32_t Aqh[2][4], Aql[2][4];
#pragma unroll
    for (int mf = 0; mf < 2; mf++) {
        uint32_t ra = sbase + SQH + (uint32_t)((wm * 32 + mf * 16 + lrow) * 48) + lkb;
        ldsm_x4(Aqh[mf][0], Aqh[mf][1], Aqh[mf][2], Aqh[mf][3], ra);
        ldsm_x4(Aql[mf][0], Aql[mf][1], Aql[mf][2], Aql[mf][3], ra + (SQL - SQH));
    }

    float oacc[2][8][4];
#pragma unroll
    for (int i = 0; i < 2; i++)
#pragma unroll
        for (int j = 0; j < 8; j++)
#pragma unroll
            for (int e = 0; e < 4; e++) oacc[i][j][e] = 0.f;
    float zv[2][2] = {{0.f, 0.f}, {0.f, 0.f}};

#define ATT_LOAD(t, bsel)                                                                \
    do {                                                                                 \
        const int j0_ = (t) * 64;                                                        \
        const uint32_t bb = sbase + S_TILES + (bsel) * A_BUFSZ;                          \
        {                                                                                \
            int arr = tid >> 7;                                                          \
            int rem = tid & 127;                                                         \
            int row = rem >> 1;                                                          \
            int ch = rem & 1;                                                            \
            const bf16* src = arr ? klo : khi;                                           \
            cp_async16(bb + arr * 3072 + row * 48 + ch * 16,                             \
                       src + (size_t)(b * Ll + j0_ + row) * 256 + h * 16 + ch * 8);      \
        }                                                                                \
        _Pragma("unroll")                                                                \
        for (int t2 = 0; t2 < 4; t2++) {                                                 \
            int idx = t2 * 256 + tid;                                                    \
            int arr = idx >> 9;                                                          \
            int rem = idx & 511;                                                         \
            int row = rem >> 3;                                                          \
            int ch = rem & 7;                                                            \
            const bf16* src = arr ? vlo : vhi;                                           \
            cp_async16(bb + 6144 + arr * 9216 + row * 144 + ch * 16,                     \
                       src + (size_t)(b * Ll + j0_ + row) * 1024 + h * 64 + ch * 8);     \
        }                                                                                \
        cp_commit();                                                                     \
    } while (0)

    ATT_LOAD(0, 0);

    const int lm = lane >> 3;   // ldsm.trans matrix index
    const int lr = lane & 7;

    for (int t = 0; t < nt; t++) {
        if (t + 1 < nt) {
            ATT_LOAD(t + 1, (t + 1) & 1);
            asm volatile("cp.async.wait_group 1;" ::: "memory");
        } else {
            asm volatile("cp.async.wait_group 0;" ::: "memory");
        }
        __syncthreads();

        const int j0 = t * 64;
        const uint32_t bb = sbase + S_TILES + (t & 1) * A_BUFSZ;

        // ---- QK^T ----
        float sacc[2][4][4];
#pragma unroll
        for (int i = 0; i < 2; i++)
#pragma unroll
            for (int j = 0; j < 4; j++)
#pragma unroll
                for (int e = 0; e < 4; e++) sacc[i][j][e] = 0.f;

#pragma unroll
        for (int nf2 = 0; nf2 < 2; nf2++) {
            uint32_t ra = bb + (uint32_t)((wn * 32 + nf2 * 16 + lrow) * 48) + lkb;
            uint32_t kh0, kh1, kh2, kh3, kl0, kl1, kl2, kl3;
            ldsm_x4(kh0, kh1, kh2, kh3, ra);
            ldsm_x4(kl0, kl1, kl2, kl3, ra + 3072);
#pragma unroll
            for (int mf = 0; mf < 2; mf++) {
                mma16816(sacc[mf][nf2 * 2 + 0], Aqh[mf][0], Aqh[mf][1], Aqh[mf][2], Aqh[mf][3], kh0, kh2);
                mma16816(sacc[mf][nf2 * 2 + 0], Aqh[mf][0], Aqh[mf][1], Aqh[mf][2], Aqh[mf][3], kl0, kl2);
                mma16816(sacc[mf][nf2 * 2 + 0], Aql[mf][0], Aql[mf][1], Aql[mf][2], Aql[mf][3], kh0, kh2);
                mma16816(sacc[mf][nf2 * 2 + 1], Aqh[mf][0], Aqh[mf][1], Aqh[mf][2], Aqh[mf][3], kh1, kh3);
                mma16816(sacc[mf][nf2 * 2 + 1], Aqh[mf][0], Aqh[mf][1], Aqh[mf][2], Aqh[mf][3], kl1, kl3);
                mma16816(sacc[mf][nf2 * 2 + 1], Aql[mf][0], Aql[mf][1], Aql[mf][2], Aql[mf][3], kh1, kh3);
            }
        }

        // ---- square, scale, mask, z, repack to A-frags ----
        uint32_t Ash[2][2][4], Asl[2][2][4];
        const bool dm = (j0 + 64 > qi0);
        const int rq = qi0 + wm * 32 + (lane >> 2);
        const int cb0 = j0 + wn * 32 + (lane & 3) * 2;
#pragma unroll
        for (int mf = 0; mf < 2; mf++) {
            const int r0 = rq + mf * 16;
            const int r1 = r0 + 8;
#pragma unroll
            for (int nf = 0; nf < 4; nf++) {
                float* c = sacc[mf][nf];
                const int cb = cb0 + nf * 8;
                float s0 = c[0] * c[0] * 0.0625f;
                float s1 = c[1] * c[1] * 0.0625f;
                float s2 = c[2] * c[2] * 0.0625f;
                float s3 = c[3] * c[3] * 0.0625f;
                if (dm) {
                    if (cb > r0) s0 = 0.f;
                    if (cb + 1 > r0) s1 = 0.f;
                    if (cb > r1) s2 = 0.f;
                    if (cb + 1 > r1) s3 = 0.f;
                }
                zv[mf][0] += s0 + s1;
                zv[mf][1] += s2 + s3;
                uint32_t h01 = packbf(s0, s1);
                uint32_t h23 = packbf(s2, s3);
                uint32_t l01 = packbf(s0 - bflo(h01), s1 - bfhi(h01));
                uint32_t l23 = packbf(s2 - bflo(h23), s3 - bfhi(h23));
                int kc = nf >> 1, nfs = nf & 1;
                Ash[mf][kc][nfs * 2 + 0] = h01;
                Ash[mf][kc][nfs * 2 + 1] = h23;
                Asl[mf][kc][nfs * 2 + 0] = l01;
                Asl[mf][kc][nfs * 2 + 1] = l23;
            }
        }

        // ---- SV: o += s @ v  (v natural layout, ldsm.trans B-frags) ----
#pragma unroll
        for (int kc = 0; kc < 2; kc++) {
#pragma unroll
            for (int nf2 = 0; nf2 < 4; nf2++) {
                // matrix lm: key block (lm&1)*8, d block (lm>>1)*8
                uint32_t av = bb + 6144 +
                              (uint32_t)((wn * 32 + kc * 16 + (lm & 1) * 8 + lr) * 144) +
                              (uint32_t)(nf2 * 32 + (lm >> 1) * 16);
                uint32_t vh0, vh1, vh2, vh3, vl0, vl1, vl2, vl3;
                ldsm_x4_t(vh0, vh1, vh2, vh3, av);
                ldsm_x4_t(vl0, vl1, vl2, vl3, av + 9216);
#pragma unroll
                for (int mf = 0; mf < 2; mf++) {
                    mma16816(oacc[mf][nf2 * 2 + 0], Ash[mf][kc][0], Ash[mf][kc][1], Ash[mf][kc][2], Ash[mf][kc][3], vh0, vh1);
                    mma16816(oacc[mf][nf2 * 2 + 0], Ash[mf][kc][0], Ash[mf][kc][1], Ash[mf][kc][2], Ash[mf][kc][3], vl0, vl1);
                    mma16816(oacc[mf][nf2 * 2 + 0], Asl[mf][kc][0], Asl[mf][kc][1], Asl[mf][kc][2], Asl[mf][kc][3], vh0, vh1);
                    mma16816(oacc[mf][nf2 * 2 + 1], Ash[mf][kc][0], Ash[mf][kc][1], Ash[mf][kc][2], Ash[mf][kc][3], vh2, vh3);
                    mma16816(oacc[mf][nf2 * 2 + 1], Ash[mf][kc][0], Ash[mf][kc][1], Ash[mf][kc][2], Ash[mf][kc][3], vl2, vl3);
                    mma16816(oacc[mf][nf2 * 2 + 1], Asl[mf][kc][0], Asl[mf][kc][1], Asl[mf][kc][2], Asl[mf][kc][3], vh2, vh3);
                }
            }
        }
        __syncthreads();
    }

    // ---- epilogue ----
#pragma unroll
    for (int mf = 0; mf < 2; mf++)
#pragma unroll
        for (int hf = 0; hf < 2; hf++) {
            zv[mf][hf] += __shfl_xor_sync(0xffffffffu, zv[mf][hf], 1);
            zv[mf][hf] += __shfl_xor_sync(0xffffffffu, zv[mf][hf], 2);
        }

    float* osm = (float*)smem_raw;
    float* zsm = (float*)(smem_raw + SZOFF);

    if (wn == 0) {
#pragma unroll
        for (int mf = 0; mf < 2; mf++) {
            int r0 = wm * 32 + mf * 16 + (lane >> 2);
#pragma unroll
            for (int nf = 0; nf < 8; nf++) {
                int col = nf * 8 + (lane & 3) * 2;
                *(float2*)&osm[r0 * OSM_STRIDE + col] = make_float2(oacc[mf][nf][0], oacc[mf][nf][1]);
                *(float2*)&osm[(r0 + 8) * OSM_STRIDE + col] = make_float2(oacc[mf][nf][2], oacc[mf][nf][3]);
            }
            if ((lane & 3) == 0) {
                zsm[r0] = zv[mf][0];
                zsm[r0 + 8] = zv[mf][1];
            }
        }
    }
    __syncthreads();
    if (wn == 1) {
#pragma unroll
        for (int mf = 0; mf < 2; mf++) {
            int r0 = wm * 32 + mf * 16 + (lane >> 2);
            float inv0 = 1.f / (zv[mf][0] + zsm[r0] + 1e-5f);
            float inv1 = 1.f / (zv[mf][1] + zsm[r0 + 8] + 1e-5f);
            size_t g0 = (size_t)(b * Ll + qi0 + r0) * 1024 + h * 64;
            size_t g1 = (size_t)(b * Ll + qi0 + r0 + 8) * 1024 + h * 64;
#pragma unroll
            for (int nf = 0; nf < 8; nf++) {
                int col = nf * 8 + (lane & 3) * 2;
                float f0 = (oacc[mf][nf][0] + osm[r0 * OSM_STRIDE + col]) * inv0;
                float f1 = (oacc[mf][nf][1] + osm[r0 * OSM_STRIDE + col + 1]) * inv0;
                float f2 = (oacc[mf][nf][2] + osm[(r0 + 8) * OSM_STRIDE + col]) * inv1;
                float f3 = (oacc[mf][nf][3] + osm[(r0 + 8) * OSM_STRIDE + col + 1]) * inv1;
                uint32_t h01 = packbf(f0, f1);
                uint32_t h23 = packbf(f2, f3);
                uint32_t l01 = packbf(f0 - bflo(h01), f1 - bfhi(h01));
                uint32_t l23 = packbf(f2 - bflo(h23), f3 - bfhi(h23));
                ((uint32_t*)ohi)[(g0 + col) >> 1] = h01;
                ((uint32_t*)olo)[(g0 + col) >> 1] = l01;
                ((uint32_t*)ohi)[(g1 + col) >> 1] = h23;
                ((uint32_t*)olo)[(g1 + col) >> 1] = l23;
            }
        }
    }
}

// ---------------------------------------------------------------------------
extern "C" void kernel_launch(void* const* d_in, const int* in_sizes, int n_in,
                              void* d_out, int out_size)
{
    const float* hidden = (const float*)d_in[0];
    const float* Wq = (const float*)d_in[1];
    const float* Wk = (const float*)d_in[2];
    const float* Wv = (const float*)d_in[3];
    const float* Wo = (const float*)d_in[4];
    float* out = (float*)d_out;

    bf16 *hhi, *hlo, *qhi, *qlo, *khi, *klo, *vhi, *vlo, *ohi, *olo;
    cudaGetSymbolAddress((void**)&hhi, g_hhi);
    cudaGetSymbolAddress((void**)&hlo, g_hlo);
    cudaGetSymbolAddress((void**)&qhi, g_qhi);
    cudaGetSymbolAddress((void**)&qlo, g_qlo);
    cudaGetSymbolAddress((void**)&khi, g_khi);
    cudaGetSymbolAddress((void**)&klo, g_klo);
    cudaGetSymbolAddress((void**)&vhi, g_vhi);
    cudaGetSymbolAddress((void**)&vlo, g_vlo);
    cudaGetSymbolAddress((void**)&ohi, g_ohi);
    cudaGetSymbolAddress((void**)&olo, g_olo);
    bf16 *wqh, *wql, *wkh, *wkl, *wvh, *wvl, *woh, *wol;
    cudaGetSymbolAddress((void**)&wqh, g_wqt_hi);
    cudaGetSymbolAddress((void**)&wql, g_wqt_lo);
    cudaGetSymbolAddress((void**)&wkh, g_wkt_hi);
    cudaGetSymbolAddress((void**)&wkl, g_wkt_lo);
    cudaGetSymbolAddress((void**)&wvh, g_wvt_hi);
    cudaGetSymbolAddress((void**)&wvl, g_wvt_lo);
    cudaGetSymbolAddress((void**)&woh, g_wot_hi);
    cudaGetSymbolAddress((void**)&wol, g_wot_lo);

    cudaFuncSetAttribute(gemm_qkv, cudaFuncAttributeMaxDynamicSharedMemorySize, GEMM_SMEM);
    cudaFuncSetAttribute(gemm_out, cudaFuncAttributeMaxDynamicSharedMemorySize, GEMM_SMEM);
    cudaFuncSetAttribute(attn_mma, cudaFuncAttributeMaxDynamicSharedMemorySize, ATT_SMEM);

    // conversions
    split_rows<<<(BL * 1024 / 4 + 255) / 256, 256>>>(hidden, hhi, hlo, BL * 1024 / 4);
    transpose_split<<<dim3(8, 32), dim3(32, 8)>>>(Wq, wqh, wql, 1024, 256);
    transpose_split<<<dim3(8, 32), dim3(32, 8)>>>(Wk, wkh, wkl, 1024, 256);
    transpose_split<<<dim3(32, 32), dim3(32, 8)>>>(Wv, wvh, wvl, 1024, 1024);
    transpose_split<<<dim3(32, 32), dim3(32, 8)>>>(Wo, woh, wol, 1024, 1024);

    // Q, K, V projections in one launch -> bf16 hi/lo
    gemm_qkv<<<384, 256, GEMM_SMEM>>>(hhi, hlo, wqh, wql, wkh, wkl, wvh, wvl,
                                      qhi, qlo, khi, klo, vhi, vlo);
    // attention -> o hi/lo
    attn_mma<<<dim3(16, Hh, Bb), 256, ATT_SMEM>>>(qhi, qlo, khi, klo, vhi, vlo, ohi, olo);
    // output projection (fp32 out)
    gemm_out<<<dim3(8, 32), 256, GEMM_SMEM>>>(ohi, olo, woh, wol, out);
}

// round 6
// speedup vs baseline: 2.1633x; 1.0331x over previous
#include <cuda_runtime.h>
#include <cuda_bf16.h>
#include <stdint.h>

// ReBasedLinearAttention: B=2, L=2048, D=1024, H=16, FD=16, HD=64
// All heavy math on mma.sync bf16 hi/lo (3-MMA fp32 emulation).
// qk_scale (1/4) folded into Q at projection time; s = (q'.k)^2 directly.

#define Bb 2
#define Ll 2048
#define Dd 1024
#define Hh 16
#define BL (Bb * Ll)

typedef unsigned long long ull;
typedef __nv_bfloat16 bf16;

// ---------------- scratch ----------------
__device__ bf16 g_hhi[BL * 1024];
__device__ bf16 g_hlo[BL * 1024];
__device__ bf16 g_qhi[BL * 256];
__device__ bf16 g_qlo[BL * 256];
__device__ bf16 g_khi[BL * 256];
__device__ bf16 g_klo[BL * 256];
__device__ bf16 g_vhi[BL * 1024];
__device__ bf16 g_vlo[BL * 1024];
__device__ bf16 g_ohi[BL * 1024];
__device__ bf16 g_olo[BL * 1024];

__device__ bf16 g_wqt_hi[256 * 1024];
__device__ bf16 g_wqt_lo[256 * 1024];
__device__ bf16 g_wkt_hi[256 * 1024];
__device__ bf16 g_wkt_lo[256 * 1024];
__device__ bf16 g_wvt_hi[1024 * 1024];
__device__ bf16 g_wvt_lo[1024 * 1024];
__device__ bf16 g_wot_hi[1024 * 1024];
__device__ bf16 g_wot_lo[1024 * 1024];

// ---------------- PTX helpers ----------------
__device__ __forceinline__ uint32_t smem_u32(const void* p) {
    uint32_t a;
    asm("{ .reg .u64 t; cvta.to.shared.u64 t, %1; cvt.u32.u64 %0, t; }" : "=r"(a) : "l"(p));
    return a;
}
__device__ __forceinline__ void cp_async16(uint32_t saddr, const void* gaddr) {
    asm volatile("cp.async.cg.shared.global [%0], [%1], 16;" :: "r"(saddr), "l"(gaddr) : "memory");
}
__device__ __forceinline__ void cp_commit() {
    asm volatile("cp.async.commit_group;" ::: "memory");
}
__device__ __forceinline__ void ldsm_x4(uint32_t& r0, uint32_t& r1, uint32_t& r2, uint32_t& r3,
                                        uint32_t addr) {
    asm volatile("ldmatrix.sync.aligned.m8n8.x4.shared.b16 {%0,%1,%2,%3}, [%4];"
                 : "=r"(r0), "=r"(r1), "=r"(r2), "=r"(r3) : "r"(addr));
}
__device__ __forceinline__ void ldsm_x4_t(uint32_t& r0, uint32_t& r1, uint32_t& r2, uint32_t& r3,
                                          uint32_t addr) {
    asm volatile("ldmatrix.sync.aligned.m8n8.x4.trans.shared.b16 {%0,%1,%2,%3}, [%4];"
                 : "=r"(r0), "=r"(r1), "=r"(r2), "=r"(r3) : "r"(addr));
}
__device__ __forceinline__ void mma16816(float c[4], uint32_t a0, uint32_t a1, uint32_t a2,
                                         uint32_t a3, uint32_t b0, uint32_t b1) {
    asm volatile(
        "mma.sync.aligned.m16n8k16.row.col.f32.bf16.bf16.f32 "
        "{%0,%1,%2,%3}, {%4,%5,%6,%7}, {%8,%9}, {%0,%1,%2,%3};"
        : "+f"(c[0]), "+f"(c[1]), "+f"(c[2]), "+f"(c[3])
        : "r"(a0), "r"(a1), "r"(a2), "r"(a3), "r"(b0), "r"(b1));
}
__device__ __forceinline__ uint32_t packbf(float flo, float fhi) {
    uint32_t r;
    asm("cvt.rn.bf16x2.f32 %0, %1, %2;" : "=r"(r) : "f"(fhi), "f"(flo));
    return r;
}
__device__ __forceinline__ float bflo(uint32_t p) { return __uint_as_float(p << 16); }
__device__ __forceinline__ float bfhi(uint32_t p) { return __uint_as_float(p & 0xffff0000u); }

// ---------------------------------------------------------------------------
// fp32 -> bf16 hi/lo split
// ---------------------------------------------------------------------------
__global__ void split_rows(const float* __restrict__ X,
                           bf16* __restrict__ hi, bf16* __restrict__ lo, int n4)
{
    int i = blockIdx.x * blockDim.x + threadIdx.x;
    if (i >= n4) return;
    float4 v = ((const float4*)X)[i];
    float vv[4] = {v.x, v.y, v.z, v.w};
    bf16 hh[4], llv[4];
#pragma unroll
    for (int j = 0; j < 4; j++) {
        bf16 h = __float2bfloat16(vv[j]);
        hh[j] = h;
        llv[j] = __float2bfloat16(vv[j] - __bfloat162float(h));
    }
    *(ull*)&hi[i * 4] = *(ull*)hh;
    *(ull*)&lo[i * 4] = *(ull*)llv;
}

// ---------------------------------------------------------------------------
// All 4 weights: W [1024,N] fp32 -> Wt hi/lo [N,1024] bf16, one launch.
// z: 0=Wq(N=256) 1=Wk(256) 2=Wv(1024) 3=Wo(1024)
// ---------------------------------------------------------------------------
__global__ void transpose_split_all(const float* __restrict__ Wq, const float* __restrict__ Wk,
                                    const float* __restrict__ Wv, const float* __restrict__ Wo,
                                    bf16* __restrict__ qh, bf16* __restrict__ ql,
                                    bf16* __restrict__ kh, bf16* __restrict__ kl,
                                    bf16* __restrict__ vh, bf16* __restrict__ vl,
                                    bf16* __restrict__ oh, bf16* __restrict__ ol)
{
    const int z = blockIdx.z;
    const int N = (z < 2) ? 256 : 1024;
    if (blockIdx.x * 32 >= N) return;
    const float* W = (z == 0) ? Wq : (z == 1) ? Wk : (z == 2) ? Wv : Wo;
    bf16* thi = (z == 0) ? qh : (z == 1) ? kh : (z == 2) ? vh : oh;
    bf16* tlo = (z == 0) ? ql : (z == 1) ? kl : (z == 2) ? vl : ol;

    __shared__ float t[32][33];
    int n0 = blockIdx.x * 32, k0 = blockIdx.y * 32;
    int tx = threadIdx.x, ty = threadIdx.y;
#pragma unroll
    for (int i = 0; i < 4; i++)
        t[ty + i * 8][tx] = W[(size_t)(k0 + ty + i * 8) * N + n0 + tx];
    __syncthreads();
#pragma unroll
    for (int i = 0; i < 4; i++) {
        int r = ty + i * 8;
        float v = t[tx][r];
        bf16 h = __float2bfloat16(v);
        bf16 l = __float2bfloat16(v - __bfloat162float(h));
        thi[(size_t)(n0 + r) * 1024 + k0 + tx] = h;
        tlo[(size_t)(n0 + r) * 1024 + k0 + tx] = l;
    }
}

// ---------------------------------------------------------------------------
// GEMM core macros
// ---------------------------------------------------------------------------
#define ROWB 80
#define MATB (128 * ROWB)
#define STAGEB (4 * MATB)
#define GEMM_SMEM (2 * STAGEB)

#define LOAD_STAGE(s, buf)                                                              \
    do {                                                                                \
        const int k0 = (s) * 32;                                                        \
        const uint32_t sb_ = sbase + (buf) * STAGEB;                                    \
        _Pragma("unroll")                                                               \
        for (int t = 0; t < 8; t++) {                                                   \
            int mat = t >> 1;                                                           \
            int sub = (t & 1) * 256 + tid;                                              \
            int row = sub >> 2;                                                         \
            int kc = sub & 3;                                                           \
            const bf16* src = (mat == 0) ? Ahi : (mat == 1) ? Alo                       \
                             : (mat == 2) ? Bhi : Blo;                                  \
            int grow = ((mat < 2) ? rowBase : colBase) + row;                           \
            const bf16* g = src + (size_t)grow * 1024 + k0 + kc * 8;                    \
            uint32_t sa = sb_ + mat * MATB + row * ROWB + kc * 16;                      \
            cp_async16(sa, g);                                                          \
        }                                                                               \
        cp_commit();                                                                    \
    } while (0)

#define GEMM_MAINLOOP()                                                                 \
    LOAD_STAGE(0, 0);                                                                   \
    for (int s = 0; s < 32; s++) {                                                      \
        if (s + 1 < 32) {                                                               \
            LOAD_STAGE(s + 1, (s + 1) & 1);                                             \
            asm volatile("cp.async.wait_group 1;" ::: "memory");                        \
        } else {                                                                        \
            asm volatile("cp.async.wait_group 0;" ::: "memory");                        \
        }                                                                               \
        __syncthreads();                                                                \
        const uint32_t sb = sbase + (s & 1) * STAGEB;                                   \
        _Pragma("unroll")                                                               \
        for (int s2 = 0; s2 < 2; s2++) {                                                \
            const uint32_t kbyte = s2 * 32 + lkb;                                       \
            uint32_t Ah[4][4], Al[4][4];                                                \
            _Pragma("unroll")                                                           \
            for (int mf = 0; mf < 4; mf++) {                                            \
                uint32_t ra = sb + (uint32_t)((wm * 64 + mf * 16 + lrow) * ROWB) + kbyte; \
                ldsm_x4(Ah[mf][0], Ah[mf][1], Ah[mf][2], Ah[mf][3], ra);                \
                ldsm_x4(Al[mf][0], Al[mf][1], Al[mf][2], Al[mf][3], ra + MATB);         \
            }                                                                           \
            uint32_t Bh[4][2], Blr[4][2];                                               \
            _Pragma("unroll")                                                           \
            for (int nf2 = 0; nf2 < 2; nf2++) {                                         \
                uint32_t rb = sb + 2 * MATB +                                           \
                              (uint32_t)((wn * 32 + nf2 * 16 + lrow) * ROWB) + kbyte;   \
                uint32_t q0, q1, q2, q3;                                                \
                ldsm_x4(q0, q1, q2, q3, rb);                                            \
                Bh[nf2 * 2 + 0][0] = q0; Bh[nf2 * 2 + 0][1] = q2;                       \
                Bh[nf2 * 2 + 1][0] = q1; Bh[nf2 * 2 + 1][1] = q3;                       \
                ldsm_x4(q0, q1, q2, q3, rb + MATB);                                     \
                Blr[nf2 * 2 + 0][0] = q0; Blr[nf2 * 2 + 0][1] = q2;                     \
                Blr[nf2 * 2 + 1][0] = q1; Blr[nf2 * 2 + 1][1] = q3;                     \
            }                                                                           \
            _Pragma("unroll")                                                           \
            for (int mf = 0; mf < 4; mf++)                                              \
                _Pragma("unroll")                                                       \
                for (int nf = 0; nf < 4; nf++) {                                        \
                    mma16816(acc[mf][nf], Ah[mf][0], Ah[mf][1], Ah[mf][2], Ah[mf][3],   \
                             Bh[nf][0], Bh[nf][1]);                                     \
                    mma16816(acc[mf][nf], Ah[mf][0], Ah[mf][1], Ah[mf][2], Ah[mf][3],   \
                             Blr[nf][0], Blr[nf][1]);                                   \
                    mma16816(acc[mf][nf], Al[mf][0], Al[mf][1], Al[mf][2], Al[mf][3],   \
                             Bh[nf][0], Bh[nf][1]);                                     \
                }                                                                       \
        }                                                                               \
        __syncthreads();                                                                \
    }

// ---------------------------------------------------------------------------
// QKV projection: one launch.  tiles: [0,64) Q, [64,128) K, [128,384) V.
// Q scaled by 0.25 (qk_scale folded in). C written as bf16 hi/lo.
// ---------------------------------------------------------------------------
__global__ __launch_bounds__(256, 2)
void gemm_qkv(const bf16* __restrict__ Ahi, const bf16* __restrict__ Alo,
              const bf16* __restrict__ qwh, const bf16* __restrict__ qwl,
              const bf16* __restrict__ kwh, const bf16* __restrict__ kwl,
              const bf16* __restrict__ vwh, const bf16* __restrict__ vwl,
              bf16* __restrict__ qh, bf16* __restrict__ ql,
              bf16* __restrict__ kh, bf16* __restrict__ kl,
              bf16* __restrict__ vh, bf16* __restrict__ vl)
{
    int t = blockIdx.x;
    const bf16 *Bhi, *Blo;
    bf16 *Chi, *Clo;
    int N, bx, by;
    float cs;
    if (t < 64) {
        Bhi = qwh; Blo = qwl; Chi = qh; Clo = ql; N = 256; cs = 0.25f;
        bx = t & 1; by = t >> 1;
    } else if (t < 128) {
        t -= 64;
        Bhi = kwh; Blo = kwl; Chi = kh; Clo = kl; N = 256; cs = 1.f;
        bx = t & 1; by = t >> 1;
    } else {
        t -= 128;
        Bhi = vwh; Blo = vwl; Chi = vh; Clo = vl; N = 1024; cs = 1.f;
        bx = t & 7; by = t >> 3;
    }

    extern __shared__ char smem_raw[];
    const uint32_t sbase = smem_u32(smem_raw);

    const int tid = threadIdx.x;
    const int lane = tid & 31;
    const int warp = tid >> 5;
    const int wm = warp >> 2;
    const int wn = warp & 3;
    const int rowBase = by * 128;
    const int colBase = bx * 128;

    float acc[4][4][4];
#pragma unroll
    for (int i = 0; i < 4; i++)
#pragma unroll
        for (int j = 0; j < 4; j++)
#pragma unroll
            for (int e = 0; e < 4; e++) acc[i][j][e] = 0.f;

    const int lrow = lane & 15;
    const int lkb = ((lane >> 4) & 1) * 16;

    GEMM_MAINLOOP();

    const int r0b = rowBase + wm * 64 + (lane >> 2);
    const int c0b = colBase + wn * 32 + (lane & 3) * 2;
#pragma unroll
    for (int mf = 0; mf < 4; mf++) {
#pragma unroll
        for (int nf = 0; nf < 4; nf++) {
            int r = r0b + mf * 16;
            int c = c0b + nf * 8;
            float a0 = acc[mf][nf][0] * cs, a1 = acc[mf][nf][1] * cs;
            float a2 = acc[mf][nf][2] * cs, a3 = acc[mf][nf][3] * cs;
            uint32_t h01 = packbf(a0, a1);
            uint32_t h23 = packbf(a2, a3);
            uint32_t l01 = packbf(a0 - bflo(h01), a1 - bfhi(h01));
            uint32_t l23 = packbf(a2 - bflo(h23), a3 - bfhi(h23));
            ((uint32_t*)Chi)[((size_t)r * N + c) >> 1] = h01;
            ((uint32_t*)Clo)[((size_t)r * N + c) >> 1] = l01;
            ((uint32_t*)Chi)[((size_t)(r + 8) * N + c) >> 1] = h23;
            ((uint32_t*)Clo)[((size_t)(r + 8) * N + c) >> 1] = l23;
        }
    }
}

// ---------------------------------------------------------------------------
// O projection: fp32 output.
// ---------------------------------------------------------------------------
__global__ __launch_bounds__(256, 2)
void gemm_out(const bf16* __restrict__ Ahi, const bf16* __restrict__ Alo,
              const bf16* __restrict__ Bhi, const bf16* __restrict__ Blo,
              float* __restrict__ C)
{
    extern __shared__ char smem_raw[];
    const uint32_t sbase = smem_u32(smem_raw);

    const int tid = threadIdx.x;
    const int lane = tid & 31;
    const int warp = tid >> 5;
    const int wm = warp >> 2;
    const int wn = warp & 3;
    const int rowBase = blockIdx.y * 128;
    const int colBase = blockIdx.x * 128;
    const int N = 1024;

    float acc[4][4][4];
#pragma unroll
    for (int i = 0; i < 4; i++)
#pragma unroll
        for (int j = 0; j < 4; j++)
#pragma unroll
            for (int e = 0; e < 4; e++) acc[i][j][e] = 0.f;

    const int lrow = lane & 15;
    const int lkb = ((lane >> 4) & 1) * 16;

    GEMM_MAINLOOP();

    const int r0b = rowBase + wm * 64 + (lane >> 2);
    const int c0b = colBase + wn * 32 + (lane & 3) * 2;
#pragma unroll
    for (int mf = 0; mf < 4; mf++) {
#pragma unroll
        for (int nf = 0; nf < 4; nf++) {
            int r = r0b + mf * 16;
            int c = c0b + nf * 8;
            *(float2*)&C[(size_t)r * N + c] = make_float2(acc[mf][nf][0], acc[mf][nf][1]);
            *(float2*)&C[(size_t)(r + 8) * N + c] = make_float2(acc[mf][nf][2], acc[mf][nf][3]);
        }
    }
}

// ---------------------------------------------------------------------------
// Tensor-core rebased attention. s = (q'.k)^2 (scale prefolded), causal.
// ---------------------------------------------------------------------------
#define SQH 0
#define SQL 6144
#define S_TILES 12288
#define A_BUFSZ 24576
#define SZOFF 61440
#define ATT_SMEM 61952
#define OSM_STRIDE 66

__global__ __launch_bounds__(256, 2)
void attn_mma(const bf16* __restrict__ qhi, const bf16* __restrict__ qlo,
              const bf16* __restrict__ khi, const bf16* __restrict__ klo,
              const bf16* __restrict__ vhi, const bf16* __restrict__ vlo,
              bf16* __restrict__ ohi, bf16* __restrict__ olo)
{
    extern __shared__ char smem_raw[];
    const uint32_t sbase = smem_u32(smem_raw);

    const int qt = 15 - (int)blockIdx.x;
    const int h = blockIdx.y;
    const int b = blockIdx.z;
    const int qi0 = qt * 128;
    const int nt = 2 * qt + 2;

    const int tid = threadIdx.x;
    const int lane = tid & 31;
    const int warp = tid >> 5;
    const int wm = warp >> 1;
    const int wn = warp & 1;
    const int lrow = lane & 15;
    const int lkb = ((lane >> 4) & 1) * 16;

#pragma unroll
    for (int t = 0; t < 2; t++) {
        int idx = t * 256 + tid;
        int arr = idx >> 8;
        int rem = idx & 255;
        int row = rem >> 1;
        int ch = rem & 1;
        const bf16* src = arr ? qlo : qhi;
        uint4 v = *(const uint4*)&src[(size_t)(b * Ll + qi0 + row) * 256 + h * 16 + ch * 8];
        *(uint4*)(smem_raw + (arr ? SQL : SQH) + row * 48 + ch * 16) = v;
    }
    __syncthreads();

    uint32_t Aqh[2][4], Aql[2][4];
#pragma unroll
    for (int mf = 0; mf < 2; mf++) {
        uint32_t ra = sbase + SQH + (uint32_t)((wm * 32 + mf * 16 + lrow) * 48) + lkb;
        ldsm_x4(Aqh[mf][0], Aqh[mf][1], Aqh[mf][2], Aqh[mf][3], ra);
        ldsm_x4(Aql[mf][0], Aql[mf][1], Aql[mf][2], Aql[mf][3], ra + (SQL - SQH));
    }

    float oacc[2][8][4];
#pragma unroll
    for (int i = 0; i < 2; i++)
#pragma unroll
        for (int j = 0; j < 8; j++)
#pragma unroll
            for (int e = 0; e < 4; e++) oacc[i][j][e] = 0.f;
    float zv[2][2] = {{0.f, 0.f}, {0.f, 0.f}};

#define ATT_LOAD(t, bsel)                                                                \
    do {                                                                                 \
        const int j0_ = (t) * 64;                                                        \
        const uint32_t bb = sbase + S_TILES + (bsel) * A_BUFSZ;                          \
        {                                                                                \
            int arr = tid >> 7;                                                          \
            int rem = tid & 127;                                                         \
            int row = rem >> 1;                                                          \
            int ch = rem & 1;                                                            \
            const bf16* src = arr ? klo : khi;                                           \
            cp_async16(bb + arr * 3072 + row * 48 + ch * 16,                             \
                       src + (size_t)(b * Ll + j0_ + row) * 256 + h * 16 + ch * 8);      \
        }                                                                                \
        _Pragma("unroll")                                                                \
        for (int t2 = 0; t2 < 4; t2++) {                                                 \
            int idx = t2 * 256 + tid;                                                    \
            int arr = idx >> 9;                                                          \
            int rem = idx & 511;                                                         \
            int row = rem >> 3;                                                          \
            int ch = rem & 7;                                                            \
            const bf16* src = arr ? vlo : vhi;                                           \
            cp_async16(bb + 6144 + arr * 9216 + row * 144 + ch * 16,                     \
                       src + (size_t)(b * Ll + j0_ + row) * 1024 + h * 64 + ch * 8);     \
        }                                                                                \
        cp_commit();                                                                     \
    } while (0)

    ATT_LOAD(0, 0);

    const int lm = lane >> 3;
    const int lr = lane & 7;

    for (int t = 0; t < nt; t++) {
        if (t + 1 < nt) {
            ATT_LOAD(t + 1, (t + 1) & 1);
            asm volatile("cp.async.wait_group 1;" ::: "memory");
        } else {
            asm volatile("cp.async.wait_group 0;" ::: "memory");
        }
        __syncthreads();

        const int j0 = t * 64;
        const uint32_t bb = sbase + S_TILES + (t & 1) * A_BUFSZ;

        // ---- QK^T ----
        float sacc[2][4][4];
#pragma unroll
        for (int i = 0; i < 2; i++)
#pragma unroll
            for (int j = 0; j < 4; j++)
#pragma unroll
                for (int e = 0; e < 4; e++) sacc[i][j][e] = 0.f;

#pragma unroll
        for (int nf2 = 0; nf2 < 2; nf2++) {
            uint32_t ra = bb + (uint32_t)((wn * 32 + nf2 * 16 + lrow) * 48) + lkb;
            uint32_t kh0, kh1, kh2, kh3, kl0, kl1, kl2, kl3;
            ldsm_x4(kh0, kh1, kh2, kh3, ra);
            ldsm_x4(kl0, kl1, kl2, kl3, ra + 3072);
#pragma unroll
            for (int mf = 0; mf < 2; mf++) {
                mma16816(sacc[mf][nf2 * 2 + 0], Aqh[mf][0], Aqh[mf][1], Aqh[mf][2], Aqh[mf][3], kh0, kh2);
                mma16816(sacc[mf][nf2 * 2 + 0], Aqh[mf][0], Aqh[mf][1], Aqh[mf][2], Aqh[mf][3], kl0, kl2);
                mma16816(sacc[mf][nf2 * 2 + 0], Aql[mf][0], Aql[mf][1], Aql[mf][2], Aql[mf][3], kh0, kh2);
                mma16816(sacc[mf][nf2 * 2 + 1], Aqh[mf][0], Aqh[mf][1], Aqh[mf][2], Aqh[mf][3], kh1, kh3);
                mma16816(sacc[mf][nf2 * 2 + 1], Aqh[mf][0], Aqh[mf][1], Aqh[mf][2], Aqh[mf][3], kl1, kl3);
                mma16816(sacc[mf][nf2 * 2 + 1], Aql[mf][0], Aql[mf][1], Aql[mf][2], Aql[mf][3], kh1, kh3);
            }
        }

        // ---- square (scale prefolded), mask (uniform branch), z, repack ----
        uint32_t Ash[2][2][4], Asl[2][2][4];
        const bool dm = (j0 + 64 > qi0);
        if (dm) {
            const int rq = qi0 + wm * 32 + (lane >> 2);
            const int cb0 = j0 + wn * 32 + (lane & 3) * 2;
#pragma unroll
            for (int mf = 0; mf < 2; mf++) {
                const int r0 = rq + mf * 16;
                const int r1 = r0 + 8;
#pragma unroll
                for (int nf = 0; nf < 4; nf++) {
                    float* c = sacc[mf][nf];
                    const int cb = cb0 + nf * 8;
                    if (cb > r0) c[0] = 0.f;
                    if (cb + 1 > r0) c[1] = 0.f;
                    if (cb > r1) c[2] = 0.f;
                    if (cb + 1 > r1) c[3] = 0.f;
                }
            }
        }
#pragma unroll
        for (int mf = 0; mf < 2; mf++) {
#pragma unroll
            for (int nf = 0; nf < 4; nf++) {
                float* c = sacc[mf][nf];
                float s0 = c[0] * c[0];
                float s1 = c[1] * c[1];
                float s2 = c[2] * c[2];
                float s3 = c[3] * c[3];
                zv[mf][0] += s0 + s1;
                zv[mf][1] += s2 + s3;
                uint32_t h01 = packbf(s0, s1);
                uint32_t h23 = packbf(s2, s3);
                uint32_t l01 = packbf(s0 - bflo(h01), s1 - bfhi(h01));
                uint32_t l23 = packbf(s2 - bflo(h23), s3 - bfhi(h23));
                int kc = nf >> 1, nfs = nf & 1;
                Ash[mf][kc][nfs * 2 + 0] = h01;
                Ash[mf][kc][nfs * 2 + 1] = h23;
                Asl[mf][kc][nfs * 2 + 0] = l01;
                Asl[mf][kc][nfs * 2 + 1] = l23;
            }
        }

        // ---- SV ----
#pragma unroll
        for (int kc = 0; kc < 2; kc++) {
#pragma unroll
            for (int nf2 = 0; nf2 < 4; nf2++) {
                uint32_t av = bb + 6144 +
                              (uint32_t)((wn * 32 + kc * 16 + (lm & 1) * 8 + lr) * 144) +
                              (uint32_t)(nf2 * 32 + (lm >> 1) * 16);
                uint32_t vh0, vh1, vh2, vh3, vl0, vl1, vl2, vl3;
                ldsm_x4_t(vh0, vh1, vh2, vh3, av);
                ldsm_x4_t(vl0, vl1, vl2, vl3, av + 9216);
#pragma unroll
                for (int mf = 0; mf < 2; mf++) {
                    mma16816(oacc[mf][nf2 * 2 + 0], Ash[mf][kc][0], Ash[mf][kc][1], Ash[mf][kc][2], Ash[mf][kc][3], vh0, vh1);
                    mma16816(oacc[mf][nf2 * 2 + 0], Ash[mf][kc][0], Ash[mf][kc][1], Ash[mf][kc][2], Ash[mf][kc][3], vl0, vl1);
                    mma16816(oacc[mf][nf2 * 2 + 0], Asl[mf][kc][0], Asl[mf][kc][1], Asl[mf][kc][2], Asl[mf][kc][3], vh0, vh1);
                    mma16816(oacc[mf][nf2 * 2 + 1], Ash[mf][kc][0], Ash[mf][kc][1], Ash[mf][kc][2], Ash[mf][kc][3], vh2, vh3);
                    mma16816(oacc[mf][nf2 * 2 + 1], Ash[mf][kc][0], Ash[mf][kc][1], Ash[mf][kc][2], Ash[mf][kc][3], vl2, vl3);
                    mma16816(oacc[mf][nf2 * 2 + 1], Asl[mf][kc][0], Asl[mf][kc][1], Asl[mf][kc][2], Asl[mf][kc][3], vh2, vh3);
                }
            }
        }
        __syncthreads();
    }

    // ---- epilogue ----
#pragma unroll
    for (int mf = 0; mf < 2; mf++)
#pragma unroll
        for (int hf = 0; hf < 2; hf++) {
            zv[mf][hf] += __shfl_xor_sync(0xffffffffu, zv[mf][hf], 1);
            zv[mf][hf] += __shfl_xor_sync(0xffffffffu, zv[mf][hf], 2);
        }

    float* osm = (float*)smem_raw;
    float* zsm = (float*)(smem_raw + SZOFF);

    if (wn == 0) {
#pragma unroll
        for (int mf = 0; mf < 2; mf++) {
            int r0 = wm * 32 + mf * 16 + (lane >> 2);
#pragma unroll
            for (int nf = 0; nf < 8; nf++) {
                int col = nf * 8 + (lane & 3) * 2;
                *(float2*)&osm[r0 * OSM_STRIDE + col] = make_float2(oacc[mf][nf][0], oacc[mf][nf][1]);
                *(float2*)&osm[(r0 + 8) * OSM_STRIDE + col] = make_float2(oacc[mf][nf][2], oacc[mf][nf][3]);
            }
            if ((lane & 3) == 0) {
                zsm[r0] = zv[mf][0];
                zsm[r0 + 8] = zv[mf][1];
            }
        }
    }
    __syncthreads();
    if (wn == 1) {
#pragma unroll
        for (int mf = 0; mf < 2; mf++) {
            int r0 = wm * 32 + mf * 16 + (lane >> 2);
            float inv0 = 1.f / (zv[mf][0] + zsm[r0] + 1e-5f);
            float inv1 = 1.f / (zv[mf][1] + zsm[r0 + 8] + 1e-5f);
            size_t g0 = (size_t)(b * Ll + qi0 + r0) * 1024 + h * 64;
            size_t g1 = (size_t)(b * Ll + qi0 + r0 + 8) * 1024 + h * 64;
#pragma unroll
            for (int nf = 0; nf < 8; nf++) {
                int col = nf * 8 + (lane & 3) * 2;
                float f0 = (oacc[mf][nf][0] + osm[r0 * OSM_STRIDE + col]) * inv0;
                float f1 = (oacc[mf][nf][1] + osm[r0 * OSM_STRIDE + col + 1]) * inv0;
                float f2 = (oacc[mf][nf][2] + osm[(r0 + 8) * OSM_STRIDE + col]) * inv1;
                float f3 = (oacc[mf][nf][3] + osm[(r0 + 8) * OSM_STRIDE + col + 1]) * inv1;
                uint32_t h01 = packbf(f0, f1);
                uint32_t h23 = packbf(f2, f3);
                uint32_t l01 = packbf(f0 - bflo(h01), f1 - bfhi(h01));
                uint32_t l23 = packbf(f2 - bflo(h23), f3 - bfhi(h23));
                ((uint32_t*)ohi)[(g0 + col) >> 1] = h01;
                ((uint32_t*)olo)[(g0 + col) >> 1] = l01;
                ((uint32_t*)ohi)[(g1 + col) >> 1] = h23;
                ((uint32_t*)olo)[(g1 + col) >> 1] = l23;
            }
        }
    }
}

// ---------------------------------------------------------------------------
extern "C" void kernel_launch(void* const* d_in, const int* in_sizes, int n_in,
                              void* d_out, int out_size)
{
    const float* hidden = (const float*)d_in[0];
    const float* Wq = (const float*)d_in[1];
    const float* Wk = (const float*)d_in[2];
    const float* Wv = (const float*)d_in[3];
    const float* Wo = (const float*)d_in[4];
    float* out = (float*)d_out;

    bf16 *hhi, *hlo, *qhi, *qlo, *khi, *klo, *vhi, *vlo, *ohi, *olo;
    cudaGetSymbolAddress((void**)&hhi, g_hhi);
    cudaGetSymbolAddress((void**)&hlo, g_hlo);
    cudaGetSymbolAddress((void**)&qhi, g_qhi);
    cudaGetSymbolAddress((void**)&qlo, g_qlo);
    cudaGetSymbolAddress((void**)&khi, g_khi);
    cudaGetSymbolAddress((void**)&klo, g_klo);
    cudaGetSymbolAddress((void**)&vhi, g_vhi);
    cudaGetSymbolAddress((void**)&vlo, g_vlo);
    cudaGetSymbolAddress((void**)&ohi, g_ohi);
    cudaGetSymbolAddress((void**)&olo, g_olo);
    bf16 *wqh, *wql, *wkh, *wkl, *wvh, *wvl, *woh, *wol;
    cudaGetSymbolAddress((void**)&wqh, g_wqt_hi);
    cudaGetSymbolAddress((void**)&wql, g_wqt_lo);
    cudaGetSymbolAddress((void**)&wkh, g_wkt_hi);
    cudaGetSymbolAddress((void**)&wkl, g_wkt_lo);
    cudaGetSymbolAddress((void**)&wvh, g_wvt_hi);
    cudaGetSymbolAddress((void**)&wvl, g_wvt_lo);
    cudaGetSymbolAddress((void**)&woh, g_wot_hi);
    cudaGetSymbolAddress((void**)&wol, g_wot_lo);

    cudaFuncSetAttribute(gemm_qkv, cudaFuncAttributeMaxDynamicSharedMemorySize, GEMM_SMEM);
    cudaFuncSetAttribute(gemm_out, cudaFuncAttributeMaxDynamicSharedMemorySize, GEMM_SMEM);
    cudaFuncSetAttribute(attn_mma, cudaFuncAttributeMaxDynamicSharedMemorySize, ATT_SMEM);

    // conversions
    split_rows<<<(BL * 1024 / 4 + 255) / 256, 256>>>(hidden, hhi, hlo, BL * 1024 / 4);
    transpose_split_all<<<dim3(32, 32, 4), dim3(32, 8)>>>(Wq, Wk, Wv, Wo,
        wqh, wql, wkh, wkl, wvh, wvl, woh, wol);

    // Q (x0.25), K, V projections -> bf16 hi/lo
    gemm_qkv<<<384, 256, GEMM_SMEM>>>(hhi, hlo, wqh, wql, wkh, wkl, wvh, wvl,
                                      qhi, qlo, khi, klo, vhi, vlo);
    // attention -> o hi/lo
    attn_mma<<<dim3(16, Hh, Bb), 256, ATT_SMEM>>>(qhi, qlo, khi, klo, vhi, vlo, ohi, olo);
    // output projection (fp32 out)
    gemm_out<<<dim3(8, 32), 256, GEMM_SMEM>>>(ohi, olo, woh, wol, out);
}

// round 7
// speedup vs baseline: 2.3282x; 1.0762x over previous
#include <cuda_runtime.h>
#include <cuda_bf16.h>
#include <stdint.h>

// ReBasedLinearAttention: B=2, L=2048, D=1024, H=16, FD=16, HD=64
// All heavy math on mma.sync bf16 hi/lo (3-MMA fp32 emulation).
// qk_scale folded into Q. Attention: paired query tiles -> 256 equal-work CTAs.

#define Bb 2
#define Ll 2048
#define Dd 1024
#define Hh 16
#define BL (Bb * Ll)

typedef unsigned long long ull;
typedef __nv_bfloat16 bf16;

// ---------------- scratch ----------------
__device__ bf16 g_hhi[BL * 1024];
__device__ bf16 g_hlo[BL * 1024];
__device__ bf16 g_qhi[BL * 256];
__device__ bf16 g_qlo[BL * 256];
__device__ bf16 g_khi[BL * 256];
__device__ bf16 g_klo[BL * 256];
__device__ bf16 g_vhi[BL * 1024];
__device__ bf16 g_vlo[BL * 1024];
__device__ bf16 g_ohi[BL * 1024];
__device__ bf16 g_olo[BL * 1024];

__device__ bf16 g_wqt_hi[256 * 1024];
__device__ bf16 g_wqt_lo[256 * 1024];
__device__ bf16 g_wkt_hi[256 * 1024];
__device__ bf16 g_wkt_lo[256 * 1024];
__device__ bf16 g_wvt_hi[1024 * 1024];
__device__ bf16 g_wvt_lo[1024 * 1024];
__device__ bf16 g_wot_hi[1024 * 1024];
__device__ bf16 g_wot_lo[1024 * 1024];

// ---------------- PTX helpers ----------------
__device__ __forceinline__ uint32_t smem_u32(const void* p) {
    uint32_t a;
    asm("{ .reg .u64 t; cvta.to.shared.u64 t, %1; cvt.u32.u64 %0, t; }" : "=r"(a) : "l"(p));
    return a;
}
__device__ __forceinline__ void cp_async16(uint32_t saddr, const void* gaddr) {
    asm volatile("cp.async.cg.shared.global [%0], [%1], 16;" :: "r"(saddr), "l"(gaddr) : "memory");
}
__device__ __forceinline__ void cp_commit() {
    asm volatile("cp.async.commit_group;" ::: "memory");
}
__device__ __forceinline__ void ldsm_x4(uint32_t& r0, uint32_t& r1, uint32_t& r2, uint32_t& r3,
                                        uint32_t addr) {
    asm volatile("ldmatrix.sync.aligned.m8n8.x4.shared.b16 {%0,%1,%2,%3}, [%4];"
                 : "=r"(r0), "=r"(r1), "=r"(r2), "=r"(r3) : "r"(addr));
}
__device__ __forceinline__ void ldsm_x4_t(uint32_t& r0, uint32_t& r1, uint32_t& r2, uint32_t& r3,
                                          uint32_t addr) {
    asm volatile("ldmatrix.sync.aligned.m8n8.x4.trans.shared.b16 {%0,%1,%2,%3}, [%4];"
                 : "=r"(r0), "=r"(r1), "=r"(r2), "=r"(r3) : "r"(addr));
}
__device__ __forceinline__ void mma16816(float c[4], uint32_t a0, uint32_t a1, uint32_t a2,
                                         uint32_t a3, uint32_t b0, uint32_t b1) {
    asm volatile(
        "mma.sync.aligned.m16n8k16.row.col.f32.bf16.bf16.f32 "
        "{%0,%1,%2,%3}, {%4,%5,%6,%7}, {%8,%9}, {%0,%1,%2,%3};"
        : "+f"(c[0]), "+f"(c[1]), "+f"(c[2]), "+f"(c[3])
        : "r"(a0), "r"(a1), "r"(a2), "r"(a3), "r"(b0), "r"(b1));
}
__device__ __forceinline__ uint32_t packbf(float flo, float fhi) {
    uint32_t r;
    asm("cvt.rn.bf16x2.f32 %0, %1, %2;" : "=r"(r) : "f"(fhi), "f"(flo));
    return r;
}
__device__ __forceinline__ float bflo(uint32_t p) { return __uint_as_float(p << 16); }
__device__ __forceinline__ float bfhi(uint32_t p) { return __uint_as_float(p & 0xffff0000u); }

// ---------------------------------------------------------------------------
// fp32 -> bf16 hi/lo split
// ---------------------------------------------------------------------------
__global__ void split_rows(const float* __restrict__ X,
                           bf16* __restrict__ hi, bf16* __restrict__ lo, int n4)
{
    int i = blockIdx.x * blockDim.x + threadIdx.x;
    if (i >= n4) return;
    float4 v = ((const float4*)X)[i];
    float vv[4] = {v.x, v.y, v.z, v.w};
    bf16 hh[4], llv[4];
#pragma unroll
    for (int j = 0; j < 4; j++) {
        bf16 h = __float2bfloat16(vv[j]);
        hh[j] = h;
        llv[j] = __float2bfloat16(vv[j] - __bfloat162float(h));
    }
    *(ull*)&hi[i * 4] = *(ull*)hh;
    *(ull*)&lo[i * 4] = *(ull*)llv;
}

// ---------------------------------------------------------------------------
// All 4 weights: W [1024,N] fp32 -> Wt hi/lo [N,1024] bf16, one launch.
// ---------------------------------------------------------------------------
__global__ void transpose_split_all(const float* __restrict__ Wq, const float* __restrict__ Wk,
                                    const float* __restrict__ Wv, const float* __restrict__ Wo,
                                    bf16* __restrict__ qh, bf16* __restrict__ ql,
                                    bf16* __restrict__ kh, bf16* __restrict__ kl,
                                    bf16* __restrict__ vh, bf16* __restrict__ vl,
                                    bf16* __restrict__ oh, bf16* __restrict__ ol)
{
    const int z = blockIdx.z;
    const int N = (z < 2) ? 256 : 1024;
    if (blockIdx.x * 32 >= N) return;
    const float* W = (z == 0) ? Wq : (z == 1) ? Wk : (z == 2) ? Wv : Wo;
    bf16* thi = (z == 0) ? qh : (z == 1) ? kh : (z == 2) ? vh : oh;
    bf16* tlo = (z == 0) ? ql : (z == 1) ? kl : (z == 2) ? vl : ol;

    __shared__ float t[32][33];
    int n0 = blockIdx.x * 32, k0 = blockIdx.y * 32;
    int tx = threadIdx.x, ty = threadIdx.y;
#pragma unroll
    for (int i = 0; i < 4; i++)
        t[ty + i * 8][tx] = W[(size_t)(k0 + ty + i * 8) * N + n0 + tx];
    __syncthreads();
#pragma unroll
    for (int i = 0; i < 4; i++) {
        int r = ty + i * 8;
        float v = t[tx][r];
        bf16 h = __float2bfloat16(v);
        bf16 l = __float2bfloat16(v - __bfloat162float(h));
        thi[(size_t)(n0 + r) * 1024 + k0 + tx] = h;
        tlo[(size_t)(n0 + r) * 1024 + k0 + tx] = l;
    }
}

// ---------------------------------------------------------------------------
// GEMM core macros
// ---------------------------------------------------------------------------
#define ROWB 80
#define MATB (128 * ROWB)
#define STAGEB (4 * MATB)
#define GEMM_SMEM (2 * STAGEB)

#define LOAD_STAGE(s, buf)                                                              \
    do {                                                                                \
        const int k0 = (s) * 32;                                                        \
        const uint32_t sb_ = sbase + (buf) * STAGEB;                                    \
        _Pragma("unroll")                                                               \
        for (int t = 0; t < 8; t++) {                                                   \
            int mat = t >> 1;                                                           \
            int sub = (t & 1) * 256 + tid;                                              \
            int row = sub >> 2;                                                         \
            int kc = sub & 3;                                                           \
            const bf16* src = (mat == 0) ? Ahi : (mat == 1) ? Alo                       \
                             : (mat == 2) ? Bhi : Blo;                                  \
            int grow = ((mat < 2) ? rowBase : colBase) + row;                           \
            const bf16* g = src + (size_t)grow * 1024 + k0 + kc * 8;                    \
            uint32_t sa = sb_ + mat * MATB + row * ROWB + kc * 16;                      \
            cp_async16(sa, g);                                                          \
        }                                                                               \
        cp_commit();                                                                    \
    } while (0)

#define GEMM_MAINLOOP()                                                                 \
    LOAD_STAGE(0, 0);                                                                   \
    for (int s = 0; s < 32; s++) {                                                      \
        if (s + 1 < 32) {                                                               \
            LOAD_STAGE(s + 1, (s + 1) & 1);                                             \
            asm volatile("cp.async.wait_group 1;" ::: "memory");                        \
        } else {                                                                        \
            asm volatile("cp.async.wait_group 0;" ::: "memory");                        \
        }                                                                               \
        __syncthreads();                                                                \
        const uint32_t sb = sbase + (s & 1) * STAGEB;                                   \
        _Pragma("unroll")                                                               \
        for (int s2 = 0; s2 < 2; s2++) {                                                \
            const uint32_t kbyte = s2 * 32 + lkb;                                       \
            uint32_t Ah[4][4], Al[4][4];                                                \
            _Pragma("unroll")                                                           \
            for (int mf = 0; mf < 4; mf++) {                                            \
                uint32_t ra = sb + (uint32_t)((wm * 64 + mf * 16 + lrow) * ROWB) + kbyte; \
                ldsm_x4(Ah[mf][0], Ah[mf][1], Ah[mf][2], Ah[mf][3], ra);                \
                ldsm_x4(Al[mf][0], Al[mf][1], Al[mf][2], Al[mf][3], ra + MATB);         \
            }                                                                           \
            uint32_t Bh[4][2], Blr[4][2];                                               \
            _Pragma("unroll")                                                           \
            for (int nf2 = 0; nf2 < 2; nf2++) {                                         \
                uint32_t rb = sb + 2 * MATB +                                           \
                              (uint32_t)((wn * 32 + nf2 * 16 + lrow) * ROWB) + kbyte;   \
                uint32_t q0, q1, q2, q3;                                                \
                ldsm_x4(q0, q1, q2, q3, rb);                                            \
                Bh[nf2 * 2 + 0][0] = q0; Bh[nf2 * 2 + 0][1] = q2;                       \
                Bh[nf2 * 2 + 1][0] = q1; Bh[nf2 * 2 + 1][1] = q3;                       \
                ldsm_x4(q0, q1, q2, q3, rb + MATB);                                     \
                Blr[nf2 * 2 + 0][0] = q0; Blr[nf2 * 2 + 0][1] = q2;                     \
                Blr[nf2 * 2 + 1][0] = q1; Blr[nf2 * 2 + 1][1] = q3;                     \
            }                                                                           \
            _Pragma("unroll")                                                           \
            for (int mf = 0; mf < 4; mf++)                                              \
                _Pragma("unroll")                                                       \
                for (int nf = 0; nf < 4; nf++) {                                        \
                    mma16816(acc[mf][nf], Ah[mf][0], Ah[mf][1], Ah[mf][2], Ah[mf][3],   \
                             Bh[nf][0], Bh[nf][1]);                                     \
                    mma16816(acc[mf][nf], Ah[mf][0], Ah[mf][1], Ah[mf][2], Ah[mf][3],   \
                             Blr[nf][0], Blr[nf][1]);                                   \
                    mma16816(acc[mf][nf], Al[mf][0], Al[mf][1], Al[mf][2], Al[mf][3],   \
                             Bh[nf][0], Bh[nf][1]);                                     \
                }                                                                       \
        }                                                                               \
        __syncthreads();                                                                \
    }

// ---------------------------------------------------------------------------
// QKV projection: one launch.  tiles: [0,64) Q, [64,128) K, [128,384) V.
// ---------------------------------------------------------------------------
__global__ __launch_bounds__(256, 2)
void gemm_qkv(const bf16* __restrict__ Ahi, const bf16* __restrict__ Alo,
              const bf16* __restrict__ qwh, const bf16* __restrict__ qwl,
              const bf16* __restrict__ kwh, const bf16* __restrict__ kwl,
              const bf16* __restrict__ vwh, const bf16* __restrict__ vwl,
              bf16* __restrict__ qh, bf16* __restrict__ ql,
              bf16* __restrict__ kh, bf16* __restrict__ kl,
              bf16* __restrict__ vh, bf16* __restrict__ vl)
{
    int t = blockIdx.x;
    const bf16 *Bhi, *Blo;
    bf16 *Chi, *Clo;
    int N, bx, by;
    float cs;
    if (t < 64) {
        Bhi = qwh; Blo = qwl; Chi = qh; Clo = ql; N = 256; cs = 0.25f;
        bx = t & 1; by = t >> 1;
    } else if (t < 128) {
        t -= 64;
        Bhi = kwh; Blo = kwl; Chi = kh; Clo = kl; N = 256; cs = 1.f;
        bx = t & 1; by = t >> 1;
    } else {
        t -= 128;
        Bhi = vwh; Blo = vwl; Chi = vh; Clo = vl; N = 1024; cs = 1.f;
        bx = t & 7; by = t >> 3;
    }

    extern __shared__ char smem_raw[];
    const uint32_t sbase = smem_u32(smem_raw);

    const int tid = threadIdx.x;
    const int lane = tid & 31;
    const int warp = tid >> 5;
    const int wm = warp >> 2;
    const int wn = warp & 3;
    const int rowBase = by * 128;
    const int colBase = bx * 128;

    float acc[4][4][4];
#pragma unroll
    for (int i = 0; i < 4; i++)
#pragma unroll
        for (int j = 0; j < 4; j++)
#pragma unroll
            for (int e = 0; e < 4; e++) acc[i][j][e] = 0.f;

    const int lrow = lane & 15;
    const int lkb = ((lane >> 4) & 1) * 16;

    GEMM_MAINLOOP();

    const int r0b = rowBase + wm * 64 + (lane >> 2);
    const int c0b = colBase + wn * 32 + (lane & 3) * 2;
#pragma unroll
    for (int mf = 0; mf < 4; mf++) {
#pragma unroll
        for (int nf = 0; nf < 4; nf++) {
            int r = r0b + mf * 16;
            int c = c0b + nf * 8;
            float a0 = acc[mf][nf][0] * cs, a1 = acc[mf][nf][1] * cs;
            float a2 = acc[mf][nf][2] * cs, a3 = acc[mf][nf][3] * cs;
            uint32_t h01 = packbf(a0, a1);
            uint32_t h23 = packbf(a2, a3);
            uint32_t l01 = packbf(a0 - bflo(h01), a1 - bfhi(h01));
            uint32_t l23 = packbf(a2 - bflo(h23), a3 - bfhi(h23));
            ((uint32_t*)Chi)[((size_t)r * N + c) >> 1] = h01;
            ((uint32_t*)Clo)[((size_t)r * N + c) >> 1] = l01;
            ((uint32_t*)Chi)[((size_t)(r + 8) * N + c) >> 1] = h23;
            ((uint32_t*)Clo)[((size_t)(r + 8) * N + c) >> 1] = l23;
        }
    }
}

// ---------------------------------------------------------------------------
// O projection: fp32 output.
// ---------------------------------------------------------------------------
__global__ __launch_bounds__(256, 2)
void gemm_out(const bf16* __restrict__ Ahi, const bf16* __restrict__ Alo,
              const bf16* __restrict__ Bhi, const bf16* __restrict__ Blo,
              float* __restrict__ C)
{
    extern __shared__ char smem_raw[];
    const uint32_t sbase = smem_u32(smem_raw);

    const int tid = threadIdx.x;
    const int lane = tid & 31;
    const int warp = tid >> 5;
    const int wm = warp >> 2;
    const int wn = warp & 3;
    const int rowBase = blockIdx.y * 128;
    const int colBase = blockIdx.x * 128;
    const int N = 1024;

    float acc[4][4][4];
#pragma unroll
    for (int i = 0; i < 4; i++)
#pragma unroll
        for (int j = 0; j < 4; j++)
#pragma unroll
            for (int e = 0; e < 4; e++) acc[i][j][e] = 0.f;

    const int lrow = lane & 15;
    const int lkb = ((lane >> 4) & 1) * 16;

    GEMM_MAINLOOP();

    const int r0b = rowBase + wm * 64 + (lane >> 2);
    const int c0b = colBase + wn * 32 + (lane & 3) * 2;
#pragma unroll
    for (int mf = 0; mf < 4; mf++) {
#pragma unroll
        for (int nf = 0; nf < 4; nf++) {
            int r = r0b + mf * 16;
            int c = c0b + nf * 8;
            *(float2*)&C[(size_t)r * N + c] = make_float2(acc[mf][nf][0], acc[mf][nf][1]);
            *(float2*)&C[(size_t)(r + 8) * N + c] = make_float2(acc[mf][nf][2], acc[mf][nf][3]);
        }
    }
}

// ---------------------------------------------------------------------------
// Tensor-core rebased attention, paired query tiles (equal-work CTAs).
// CTA = (pair, h, b): processes qt = 15-pair then qt = pair. 34 tiles total.
// ---------------------------------------------------------------------------
#define SQH 0
#define SQL 6144
#define S_TILES 12288
#define A_BUFSZ 24576
#define SZOFF 61440
#define ATT_SMEM 61952
#define OSM_STRIDE 66

__global__ __launch_bounds__(256, 2)
void attn_mma(const bf16* __restrict__ qhi, const bf16* __restrict__ qlo,
              const bf16* __restrict__ khi, const bf16* __restrict__ klo,
              const bf16* __restrict__ vhi, const bf16* __restrict__ vlo,
              bf16* __restrict__ ohi, bf16* __restrict__ olo)
{
    extern __shared__ char smem_raw[];
    const uint32_t sbase = smem_u32(smem_raw);

    const int pr = blockIdx.x;   // 0..7
    const int h = blockIdx.y;
    const int b = blockIdx.z;

    const int tid = threadIdx.x;
    const int lane = tid & 31;
    const int warp = tid >> 5;
    const int wm = warp >> 1;
    const int wn = warp & 1;
    const int lrow = lane & 15;
    const int lkb = ((lane >> 4) & 1) * 16;
    const int lm = lane >> 3;
    const int lr = lane & 7;

#define ATT_LOAD(t, bsel)                                                                \
    do {                                                                                 \
        const int j0_ = (t) * 64;                                                        \
        const uint32_t bb = sbase + S_TILES + (bsel) * A_BUFSZ;                          \
        {                                                                                \
            int arr = tid >> 7;                                                          \
            int rem = tid & 127;                                                         \
            int row = rem >> 1;                                                          \
            int ch = rem & 1;                                                            \
            const bf16* src = arr ? klo : khi;                                           \
            cp_async16(bb + arr * 3072 + row * 48 + ch * 16,                             \
                       src + (size_t)(b * Ll + j0_ + row) * 256 + h * 16 + ch * 8);      \
        }                                                                                \
        _Pragma("unroll")                                                                \
        for (int t2 = 0; t2 < 4; t2++) {                                                 \
            int idx = t2 * 256 + tid;                                                    \
            int arr = idx >> 9;                                                          \
            int rem = idx & 511;                                                         \
            int row = rem >> 3;                                                          \
            int ch = rem & 7;                                                            \
            const bf16* src = arr ? vlo : vhi;                                           \
            cp_async16(bb + 6144 + arr * 9216 + row * 144 + ch * 16,                     \
                       src + (size_t)(b * Ll + j0_ + row) * 1024 + h * 64 + ch * 8);     \
        }                                                                                \
        cp_commit();                                                                     \
    } while (0)

    for (int half = 0; half < 2; half++) {
        const int qt = (half == 0) ? (15 - pr) : pr;
        const int qi0 = qt * 128;
        const int nt = 2 * qt + 2;

        // ---- load q tile (128 x 16, hi+lo) ----
#pragma unroll
        for (int t = 0; t < 2; t++) {
            int idx = t * 256 + tid;
            int arr = idx >> 8;
            int rem = idx & 255;
            int row = rem >> 1;
            int ch = rem & 1;
            const bf16* src = arr ? qlo : qhi;
            uint4 v = *(const uint4*)&src[(size_t)(b * Ll + qi0 + row) * 256 + h * 16 + ch * 8];
            *(uint4*)(smem_raw + (arr ? SQL : SQH) + row * 48 + ch * 16) = v;
        }
        __syncthreads();

        uint32_t Aqh[2][4], Aql[2][4];
#pragma unroll
        for (int mf = 0; mf < 2; mf++) {
            uint32_t ra = sbase + SQH + (uint32_t)((wm * 32 + mf * 16 + lrow) * 48) + lkb;
            ldsm_x4(Aqh[mf][0], Aqh[mf][1], Aqh[mf][2], Aqh[mf][3], ra);
            ldsm_x4(Aql[mf][0], Aql[mf][1], Aql[mf][2], Aql[mf][3], ra + (SQL - SQH));
        }

        float oacc[2][8][4];
#pragma unroll
        for (int i = 0; i < 2; i++)
#pragma unroll
            for (int j = 0; j < 8; j++)
#pragma unroll
                for (int e = 0; e < 4; e++) oacc[i][j][e] = 0.f;
        float zv[2][2] = {{0.f, 0.f}, {0.f, 0.f}};

        ATT_LOAD(0, 0);

        for (int t = 0; t < nt; t++) {
            if (t + 1 < nt) {
                ATT_LOAD(t + 1, (t + 1) & 1);
                asm volatile("cp.async.wait_group 1;" ::: "memory");
            } else {
                asm volatile("cp.async.wait_group 0;" ::: "memory");
            }
            __syncthreads();

            const int j0 = t * 64;
            const uint32_t bb = sbase + S_TILES + (t & 1) * A_BUFSZ;

            // ---- QK^T ----
            float sacc[2][4][4];
#pragma unroll
            for (int i = 0; i < 2; i++)
#pragma unroll
                for (int j = 0; j < 4; j++)
#pragma unroll
                    for (int e = 0; e < 4; e++) sacc[i][j][e] = 0.f;

#pragma unroll
            for (int nf2 = 0; nf2 < 2; nf2++) {
                uint32_t ra = bb + (uint32_t)((wn * 32 + nf2 * 16 + lrow) * 48) + lkb;
                uint32_t kh0, kh1, kh2, kh3, kl0, kl1, kl2, kl3;
                ldsm_x4(kh0, kh1, kh2, kh3, ra);
                ldsm_x4(kl0, kl1, kl2, kl3, ra + 3072);
#pragma unroll
                for (int mf = 0; mf < 2; mf++) {
                    mma16816(sacc[mf][nf2 * 2 + 0], Aqh[mf][0], Aqh[mf][1], Aqh[mf][2], Aqh[mf][3], kh0, kh2);
                    mma16816(sacc[mf][nf2 * 2 + 0], Aqh[mf][0], Aqh[mf][1], Aqh[mf][2], Aqh[mf][3], kl0, kl2);
                    mma16816(sacc[mf][nf2 * 2 + 0], Aql[mf][0], Aql[mf][1], Aql[mf][2], Aql[mf][3], kh0, kh2);
                    mma16816(sacc[mf][nf2 * 2 + 1], Aqh[mf][0], Aqh[mf][1], Aqh[mf][2], Aqh[mf][3], kh1, kh3);
                    mma16816(sacc[mf][nf2 * 2 + 1], Aqh[mf][0], Aqh[mf][1], Aqh[mf][2], Aqh[mf][3], kl1, kl3);
                    mma16816(sacc[mf][nf2 * 2 + 1], Aql[mf][0], Aql[mf][1], Aql[mf][2], Aql[mf][3], kh1, kh3);
                }
            }

            // ---- mask (uniform branch), square, z, repack ----
            uint32_t Ash[2][2][4], Asl[2][2][4];
            const bool dm = (j0 + 64 > qi0);
            if (dm) {
                const int rq = qi0 + wm * 32 + (lane >> 2);
                const int cb0 = j0 + wn * 32 + (lane & 3) * 2;
#pragma unroll
                for (int mf = 0; mf < 2; mf++) {
                    const int r0 = rq + mf * 16;
                    const int r1 = r0 + 8;
#pragma unroll
                    for (int nf = 0; nf < 4; nf++) {
                        float* c = sacc[mf][nf];
                        const int cb = cb0 + nf * 8;
                        if (cb > r0) c[0] = 0.f;
                        if (cb + 1 > r0) c[1] = 0.f;
                        if (cb > r1) c[2] = 0.f;
                        if (cb + 1 > r1) c[3] = 0.f;
                    }
                }
            }
#pragma unroll
            for (int mf = 0; mf < 2; mf++) {
#pragma unroll
                for (int nf = 0; nf < 4; nf++) {
                    float* c = sacc[mf][nf];
                    float s0 = c[0] * c[0];
                    float s1 = c[1] * c[1];
                    float s2 = c[2] * c[2];
                    float s3 = c[3] * c[3];
                    zv[mf][0] += s0 + s1;
                    zv[mf][1] += s2 + s3;
                    uint32_t h01 = packbf(s0, s1);
                    uint32_t h23 = packbf(s2, s3);
                    uint32_t l01 = packbf(s0 - bflo(h01), s1 - bfhi(h01));
                    uint32_t l23 = packbf(s2 - bflo(h23), s3 - bfhi(h23));
                    int kc = nf >> 1, nfs = nf & 1;
                    Ash[mf][kc][nfs * 2 + 0] = h01;
                    Ash[mf][kc][nfs * 2 + 1] = h23;
                    Asl[mf][kc][nfs * 2 + 0] = l01;
                    Asl[mf][kc][nfs * 2 + 1] = l23;
                }
            }

            // ---- SV ----
#pragma unroll
            for (int kc = 0; kc < 2; kc++) {
#pragma unroll
                for (int nf2 = 0; nf2 < 4; nf2++) {
                    uint32_t av = bb + 6144 +
                                  (uint32_t)((wn * 32 + kc * 16 + (lm & 1) * 8 + lr) * 144) +
                                  (uint32_t)(nf2 * 32 + (lm >> 1) * 16);
                    uint32_t vh0, vh1, vh2, vh3, vl0, vl1, vl2, vl3;
                    ldsm_x4_t(vh0, vh1, vh2, vh3, av);
                    ldsm_x4_t(vl0, vl1, vl2, vl3, av + 9216);
#pragma unroll
                    for (int mf = 0; mf < 2; mf++) {
                        mma16816(oacc[mf][nf2 * 2 + 0], Ash[mf][kc][0], Ash[mf][kc][1], Ash[mf][kc][2], Ash[mf][kc][3], vh0, vh1);
                        mma16816(oacc[mf][nf2 * 2 + 0], Ash[mf][kc][0], Ash[mf][kc][1], Ash[mf][kc][2], Ash[mf][kc][3], vl0, vl1);
                        mma16816(oacc[mf][nf2 * 2 + 0], Asl[mf][kc][0], Asl[mf][kc][1], Asl[mf][kc][2], Asl[mf][kc][3], vh0, vh1);
                        mma16816(oacc[mf][nf2 * 2 + 1], Ash[mf][kc][0], Ash[mf][kc][1], Ash[mf][kc][2], Ash[mf][kc][3], vh2, vh3);
                        mma16816(oacc[mf][nf2 * 2 + 1], Ash[mf][kc][0], Ash[mf][kc][1], Ash[mf][kc][2], Ash[mf][kc][3], vl2, vl3);
                        mma16816(oacc[mf][nf2 * 2 + 1], Asl[mf][kc][0], Asl[mf][kc][1], Asl[mf][kc][2], Asl[mf][kc][3], vh2, vh3);
                    }
                }
            }
            __syncthreads();
        }

        // ---- epilogue for this half ----
#pragma unroll
        for (int mf = 0; mf < 2; mf++)
#pragma unroll
            for (int hf = 0; hf < 2; hf++) {
                zv[mf][hf] += __shfl_xor_sync(0xffffffffu, zv[mf][hf], 1);
                zv[mf][hf] += __shfl_xor_sync(0xffffffffu, zv[mf][hf], 2);
            }

        float* osm = (float*)smem_raw;
        float* zsm = (float*)(smem_raw + SZOFF);

        if (wn == 0) {
#pragma unroll
            for (int mf = 0; mf < 2; mf++) {
                int r0 = wm * 32 + mf * 16 + (lane >> 2);
#pragma unroll
                for (int nf = 0; nf < 8; nf++) {
                    int col = nf * 8 + (lane & 3) * 2;
                    *(float2*)&osm[r0 * OSM_STRIDE + col] = make_float2(oacc[mf][nf][0], oacc[mf][nf][1]);
                    *(float2*)&osm[(r0 + 8) * OSM_STRIDE + col] = make_float2(oacc[mf][nf][2], oacc[mf][nf][3]);
                }
                if ((lane & 3) == 0) {
                    zsm[r0] = zv[mf][0];
                    zsm[r0 + 8] = zv[mf][1];
                }
            }
        }
        __syncthreads();
        if (wn == 1) {
#pragma unroll
            for (int mf = 0; mf < 2; mf++) {
                int r0 = wm * 32 + mf * 16 + (lane >> 2);
                float inv0 = 1.f / (zv[mf][0] + zsm[r0] + 1e-5f);
                float inv1 = 1.f / (zv[mf][1] + zsm[r0 + 8] + 1e-5f);
                size_t g0 = (size_t)(b * Ll + qi0 + r0) * 1024 + h * 64;
                size_t g1 = (size_t)(b * Ll + qi0 + r0 + 8) * 1024 + h * 64;
#pragma unroll
                for (int nf = 0; nf < 8; nf++) {
                    int col = nf * 8 + (lane & 3) * 2;
                    float f0 = (oacc[mf][nf][0] + osm[r0 * OSM_STRIDE + col]) * inv0;
                    float f1 = (oacc[mf][nf][1] + osm[r0 * OSM_STRIDE + col + 1]) * inv0;
                    float f2 = (oacc[mf][nf][2] + osm[(r0 + 8) * OSM_STRIDE + col]) * inv1;
                    float f3 = (oacc[mf][nf][3] + osm[(r0 + 8) * OSM_STRIDE + col + 1]) * inv1;
                    uint32_t h01 = packbf(f0, f1);
                    uint32_t h23 = packbf(f2, f3);
                    uint32_t l01 = packbf(f0 - bflo(h01), f1 - bfhi(h01));
                    uint32_t l23 = packbf(f2 - bflo(h23), f3 - bfhi(h23));
                    ((uint32_t*)ohi)[(g0 + col) >> 1] = h01;
                    ((uint32_t*)olo)[(g0 + col) >> 1] = l01;
                    ((uint32_t*)ohi)[(g1 + col) >> 1] = h23;
                    ((uint32_t*)olo)[(g1 + col) >> 1] = l23;
                }
            }
        }
        __syncthreads();   // epilogue reads done before next half's q store
    }
}

// ---------------------------------------------------------------------------
extern "C" void kernel_launch(void* const* d_in, const int* in_sizes, int n_in,
                              void* d_out, int out_size)
{
    const float* hidden = (const float*)d_in[0];
    const float* Wq = (const float*)d_in[1];
    const float* Wk = (const float*)d_in[2];
    const float* Wv = (const float*)d_in[3];
    const float* Wo = (const float*)d_in[4];
    float* out = (float*)d_out;

    bf16 *hhi, *hlo, *qhi, *qlo, *khi, *klo, *vhi, *vlo, *ohi, *olo;
    cudaGetSymbolAddress((void**)&hhi, g_hhi);
    cudaGetSymbolAddress((void**)&hlo, g_hlo);
    cudaGetSymbolAddress((void**)&qhi, g_qhi);
    cudaGetSymbolAddress((void**)&qlo, g_qlo);
    cudaGetSymbolAddress((void**)&khi, g_khi);
    cudaGetSymbolAddress((void**)&klo, g_klo);
    cudaGetSymbolAddress((void**)&vhi, g_vhi);
    cudaGetSymbolAddress((void**)&vlo, g_vlo);
    cudaGetSymbolAddress((void**)&ohi, g_ohi);
    cudaGetSymbolAddress((void**)&olo, g_olo);
    bf16 *wqh, *wql, *wkh, *wkl, *wvh, *wvl, *woh, *wol;
    cudaGetSymbolAddress((void**)&wqh, g_wqt_hi);
    cudaGetSymbolAddress((void**)&wql, g_wqt_lo);
    cudaGetSymbolAddress((void**)&wkh, g_wkt_hi);
    cudaGetSymbolAddress((void**)&wkl, g_wkt_lo);
    cudaGetSymbolAddress((void**)&wvh, g_wvt_hi);
    cudaGetSymbolAddress((void**)&wvl, g_wvt_lo);
    cudaGetSymbolAddress((void**)&woh, g_wot_hi);
    cudaGetSymbolAddress((void**)&wol, g_wot_lo);

    cudaFuncSetAttribute(gemm_qkv, cudaFuncAttributeMaxDynamicSharedMemorySize, GEMM_SMEM);
    cudaFuncSetAttribute(gemm_out, cudaFuncAttributeMaxDynamicSharedMemorySize, GEMM_SMEM);
    cudaFuncSetAttribute(attn_mma, cudaFuncAttributeMaxDynamicSharedMemorySize, ATT_SMEM);

    split_rows<<<(BL * 1024 / 4 + 255) / 256, 256>>>(hidden, hhi, hlo, BL * 1024 / 4);
    transpose_split_all<<<dim3(32, 32, 4), dim3(32, 8)>>>(Wq, Wk, Wv, Wo,
        wqh, wql, wkh, wkl, wvh, wvl, woh, wol);

    gemm_qkv<<<384, 256, GEMM_SMEM>>>(hhi, hlo, wqh, wql, wkh, wkl, wvh, wvl,
                                      qhi, qlo, khi, klo, vhi, vlo);
    attn_mma<<<dim3(8, Hh, Bb), 256, ATT_SMEM>>>(qhi, qlo, khi, klo, vhi, vlo, ohi, olo);
    gemm_out<<<dim3(8, 32), 256, GEMM_SMEM>>>(ohi, olo, woh, wol, out);
}